// round 13
// baseline (speedup 1.0000x reference)
#include <cuda_runtime.h>
#include <cuda_bf16.h>
#include <cstdint>

#define B_   4
#define N_   1024
#define DIM_ 512
#define H_   8
#define D_   64
#define BH_  32
#define SCALE_ 0.125f

#define S32  40     // smem row stride (elems) for K-chunk-32 tiles
#define S64  72     // smem row stride (elems) for 64-wide tiles

// ---------------------------------------------------------------------------
// Global scratch
// ---------------------------------------------------------------------------
__device__ __nv_bfloat16 xb_hi[4096 * 512], xb_lo[4096 * 512];
__device__ __nv_bfloat16 wqkvT_hi[1536 * 512], wqkvT_lo[1536 * 512];
__device__ __nv_bfloat16 woutT_hi[512 * 512], woutT_lo[512 * 512];
__device__ __nv_bfloat16 qb_hi[BH_ * N_ * D_], qb_lo[BH_ * N_ * D_];
__device__ __nv_bfloat16 kb_hi[BH_ * N_ * D_], kb_lo[BH_ * N_ * D_];
__device__ __nv_bfloat16 vb_hi[BH_ * N_ * D_], vb_lo[BH_ * N_ * D_];
__device__ __nv_bfloat16 vbT_hi[BH_ * D_ * N_], vbT_lo[BH_ * D_ * N_];
__device__ __nv_bfloat16 ob_hi[4096 * 512], ob_lo[4096 * 512];

// ---------------------------------------------------------------------------
// Helpers
// ---------------------------------------------------------------------------
__device__ __forceinline__ void f32split(float v, __nv_bfloat16& h, __nv_bfloat16& l) {
    h = __float2bfloat16(v);
    l = __float2bfloat16(v - __bfloat162float(h));
}
__device__ __forceinline__ uint32_t pack2(__nv_bfloat16 a, __nv_bfloat16 b) {
    return (uint32_t)__bfloat16_as_ushort(a) |
           ((uint32_t)__bfloat16_as_ushort(b) << 16);
}
__device__ __forceinline__ uint32_t packsplit(float v0, float v1,
                                              __nv_bfloat16& l0, __nv_bfloat16& l1) {
    __nv_bfloat16 h0, h1;
    f32split(v0, h0, l0); f32split(v1, h1, l1);
    return pack2(h0, h1);
}

__device__ __forceinline__ void mma16816(float* c, const uint32_t* a, const uint32_t* b) {
    asm volatile(
        "mma.sync.aligned.m16n8k16.row.col.f32.bf16.bf16.f32 "
        "{%0,%1,%2,%3}, {%4,%5,%6,%7}, {%8,%9}, {%0,%1,%2,%3};"
        : "+f"(c[0]), "+f"(c[1]), "+f"(c[2]), "+f"(c[3])
        : "r"(a[0]), "r"(a[1]), "r"(a[2]), "r"(a[3]), "r"(b[0]), "r"(b[1]));
}

__device__ __forceinline__ uint32_t smaddr(const void* p) {
    uint32_t a;
    asm("{ .reg .u64 t; cvta.to.shared.u64 t, %1; cvt.u32.u64 %0, t; }"
        : "=r"(a) : "l"(p));
    return a;
}
__device__ __forceinline__ void ldsm4(uint32_t* r, uint32_t a) {
    asm volatile("ldmatrix.sync.aligned.m8n8.x4.shared.b16 {%0,%1,%2,%3}, [%4];"
                 : "=r"(r[0]), "=r"(r[1]), "=r"(r[2]), "=r"(r[3]) : "r"(a));
}

__device__ __forceinline__ void cpa16(__nv_bfloat16* dst, const __nv_bfloat16* src) {
    uint32_t s;
    asm("{ .reg .u64 t; cvta.to.shared.u64 t, %1; cvt.u32.u64 %0, t; }"
        : "=r"(s) : "l"(dst));
    asm volatile("cp.async.cg.shared.global [%0], [%1], 16;" :: "r"(s), "l"(src));
}
#define CP_COMMIT() asm volatile("cp.async.commit_group;" ::: "memory")
#define CP_WAIT0()  asm volatile("cp.async.wait_group 0;" ::: "memory")
#define CP_WAIT1()  asm volatile("cp.async.wait_group 1;" ::: "memory")

template<int S>
__device__ __forceinline__ void tile_async32(__nv_bfloat16* dst, const __nv_bfloat16* g,
                                             int rows, int gstride, int tid) {
    for (int i = tid; i < rows * 4; i += 256) {
        int r = i >> 2, q = i & 3;
        cpa16(dst + r * S + q * 8, g + (size_t)r * gstride + q * 8);
    }
}
template<int S>
__device__ __forceinline__ void tile_async64(__nv_bfloat16* dst, const __nv_bfloat16* g,
                                             int rows, int gstride, int tid) {
    for (int i = tid; i < rows * 8; i += 256) {
        int r = i >> 3, q = i & 7;
        cpa16(dst + r * S + q * 8, g + (size_t)r * gstride + q * 8);
    }
}

__device__ __forceinline__ float warp_max(float v) {
#pragma unroll
    for (int o = 16; o; o >>= 1) v = fmaxf(v, __shfl_xor_sync(0xffffffffu, v, o));
    return v;
}
__device__ __forceinline__ float warp_sum(float v) {
#pragma unroll
    for (int o = 16; o; o >>= 1) v += __shfl_xor_sync(0xffffffffu, v, o);
    return v;
}

// ---------------------------------------------------------------------------
// Conversion prologue
// ---------------------------------------------------------------------------
__global__ void __launch_bounds__(256) conv_x(const float* __restrict__ x) {
    int i = blockIdx.x * 256 + threadIdx.x;
    float4 v = ((const float4*)x)[i];
    __nv_bfloat16 l0, l1, l2, l3;
    uint32_t h01 = packsplit(v.x, v.y, l0, l1);
    uint32_t h23 = packsplit(v.z, v.w, l2, l3);
    *(uint2*)(xb_hi + (size_t)i * 4) = make_uint2(h01, h23);
    *(uint2*)(xb_lo + (size_t)i * 4) = make_uint2(pack2(l0, l1), pack2(l2, l3));
}

__global__ void __launch_bounds__(256) conv_w(const float* __restrict__ w,
                                              __nv_bfloat16* th, __nv_bfloat16* tl,
                                              int cols) {
    int i = blockIdx.x * 256 + threadIdx.x;       // i = n*512 + k
    int n = i >> 9, k = i & 511;
    float v = w[(size_t)k * cols + n];
    __nv_bfloat16 h, l;
    f32split(v, h, l);
    th[i] = h; tl[i] = l;
}

// ---------------------------------------------------------------------------
// 2x4-warp GEMM core for 128x64 tiles (qkv / out)
// ---------------------------------------------------------------------------
template<int S, int KC>
__device__ __forceinline__ void gemm_tile24(float c[2][4][4], const __nv_bfloat16* st,
                                            int wm0, int wn0, int lane) {
    const int r8 = lane & 7, sel = lane >> 3;
    const uint32_t base = smaddr(st);
    const uint32_t TA = 128 * S * 2, TB = 64 * S * 2;
    const uint32_t aOff = ((wm0 + (sel & 1) * 8 + r8) * S + (sel >> 1) * 8) * 2;
    const uint32_t bOff = ((wn0 + (sel >> 1) * 8 + r8) * S + (sel & 1) * 8) * 2;
    const uint32_t aH0 = base + aOff, aL0 = base + TA + aOff;
    const uint32_t bH0 = base + 2 * TA + bOff, bL0 = base + 2 * TA + TB + bOff;
#pragma unroll
    for (int k0 = 0; k0 < KC; k0 += 16) {
        uint32_t aH[2][4], aL[2][4], bH[4][2], bL[4][2];
#pragma unroll
        for (int mf = 0; mf < 2; mf++) {
            ldsm4(aH[mf], aH0 + mf * (16 * S * 2) + k0 * 2);
            ldsm4(aL[mf], aL0 + mf * (16 * S * 2) + k0 * 2);
        }
#pragma unroll
        for (int p = 0; p < 2; p++) {
            uint32_t t[4];
            ldsm4(t, bH0 + p * (16 * S * 2) + k0 * 2);
            bH[2 * p][0] = t[0]; bH[2 * p][1] = t[1];
            bH[2 * p + 1][0] = t[2]; bH[2 * p + 1][1] = t[3];
            ldsm4(t, bL0 + p * (16 * S * 2) + k0 * 2);
            bL[2 * p][0] = t[0]; bL[2 * p][1] = t[1];
            bL[2 * p + 1][0] = t[2]; bL[2 * p + 1][1] = t[3];
        }
#pragma unroll
        for (int mf = 0; mf < 2; mf++)
#pragma unroll
            for (int nf = 0; nf < 4; nf++) {
                mma16816(c[mf][nf], aH[mf], bH[nf]);
                mma16816(c[mf][nf], aH[mf], bL[nf]);
                mma16816(c[mf][nf], aL[mf], bH[nf]);
            }
    }
}

#define STG_E ((2 * 128 + 2 * 64) * S32)
#define PIPE_SMEM (3 * STG_E * 2)

__device__ __forceinline__ void pipe_load(__nv_bfloat16* st,
                                          const __nv_bfloat16* aH, const __nv_bfloat16* aL,
                                          const __nv_bfloat16* bH, const __nv_bfloat16* bL,
                                          int astride, int tid) {
    tile_async32<S32>(st, aH, 128, astride, tid);
    tile_async32<S32>(st + 128 * S32, aL, 128, astride, tid);
    tile_async32<S32>(st + 2 * 128 * S32, bH, 64, astride, tid);
    tile_async32<S32>(st + 2 * 128 * S32 + 64 * S32, bL, 64, astride, tid);
}

template<int NC>
__device__ __forceinline__ void pipe_gemm(float c[2][4][4], __nv_bfloat16* smp,
                                          const __nv_bfloat16* gah, const __nv_bfloat16* gal,
                                          const __nv_bfloat16* gbh, const __nv_bfloat16* gbl,
                                          int astride, int tid, int wm0, int wn0, int lane) {
    pipe_load(smp, gah, gal, gbh, gbl, astride, tid);
    CP_COMMIT();
    pipe_load(smp + STG_E, gah + 32, gal + 32, gbh + 32, gbl + 32, astride, tid);
    CP_COMMIT();
#pragma unroll 1
    for (int ch = 0; ch < NC; ch++) {
        CP_WAIT1();
        __syncthreads();
        if (ch + 2 < NC) {
            int nx = (ch + 2) % 3;
            pipe_load(smp + nx * STG_E, gah + (ch + 2) * 32, gal + (ch + 2) * 32,
                      gbh + (ch + 2) * 32, gbl + (ch + 2) * 32, astride, tid);
        }
        CP_COMMIT();
        gemm_tile24<S32, 32>(c, smp + (ch % 3) * STG_E, wm0, wn0, lane);
    }
}

// ---------------------------------------------------------------------------
// qkv = x @ w_qkv  (M=4096, N=1536, K=512): tile 128x64
// ---------------------------------------------------------------------------
__global__ void __launch_bounds__(256, 2) qkv_mma() {
    extern __shared__ __nv_bfloat16 smp[];
    const int tid = threadIdx.x, wid = tid >> 5, lane = tid & 31;
    const int q = lane & 3, g = lane >> 2;
    const int row0 = blockIdx.y * 128, col0 = blockIdx.x * 64;
    const int wm0 = (wid & 3) * 32, wn0 = (wid >> 2) * 32;

    float c[2][4][4] = {};
    pipe_gemm<16>(c, smp,
                  xb_hi + (size_t)row0 * 512, xb_lo + (size_t)row0 * 512,
                  wqkvT_hi + (size_t)col0 * 512, wqkvT_lo + (size_t)col0 * 512,
                  512, tid, wm0, wn0, lane);

    const int part = col0 >> 9;
    const int head = (col0 >> 6) & 7;
    __nv_bfloat16* dh = part == 0 ? qb_hi : part == 1 ? kb_hi : vb_hi;
    __nv_bfloat16* dl = part == 0 ? qb_lo : part == 1 ? kb_lo : vb_lo;
    const float sc = part == 0 ? SCALE_ : 1.0f;
#pragma unroll
    for (int mf = 0; mf < 2; mf++)
#pragma unroll
        for (int nf = 0; nf < 4; nf++) {
            int d = wn0 + nf * 8 + q * 2;
#pragma unroll
            for (int half = 0; half < 2; half++) {
                int m = row0 + wm0 + mf * 16 + g + half * 8;
                __nv_bfloat16 l0, l1;
                uint32_t hp = packsplit(c[mf][nf][half * 2] * sc,
                                        c[mf][nf][half * 2 + 1] * sc, l0, l1);
                size_t base = ((size_t)((m >> 10) * 8 + head) * 1024 + (m & 1023)) * 64 + d;
                *(uint32_t*)(dh + base) = hp;
                *(uint32_t*)(dl + base) = pack2(l0, l1);
            }
        }
}

// ---------------------------------------------------------------------------
// V transpose: vb [bh][j][d] -> vbT [bh][d][j]
// ---------------------------------------------------------------------------
__global__ void __launch_bounds__(256) vtrans() {
    __shared__ __nv_bfloat16 th[32][33], tl[32][33];
    const int bh = blockIdx.z, j0 = blockIdx.x * 32, d0 = blockIdx.y * 32;
    const int tx = threadIdx.x & 31, ty = threadIdx.x >> 5;
    const size_t src = ((size_t)bh * 1024 + j0) * 64 + d0;
    for (int r = ty; r < 32; r += 8) {
        th[r][tx] = vb_hi[src + (size_t)r * 64 + tx];
        tl[r][tx] = vb_lo[src + (size_t)r * 64 + tx];
    }
    __syncthreads();
    const size_t dst = ((size_t)bh * 64 + d0) * 1024 + j0;
    for (int r = ty; r < 32; r += 8) {
        vbT_hi[dst + (size_t)r * 1024 + tx] = th[tx][r];
        vbT_lo[dst + (size_t)r * 1024 + tx] = tl[tx][r];
    }
}

// ---------------------------------------------------------------------------
// FUSED attention: sim (QK^T) -> entmax-1.5 -> attn @ V, one CTA per
// (bh, 32-row block). Scores live in a 32-row smem buffer; attn overwrites
// it in place as bf16 hi/lo and feeds ldmatrix for the AV phase.
// ---------------------------------------------------------------------------
#define FA_QH   0
#define FA_QL   4608
#define FA_ROW  9216
#define FA_RPITCH 4240                       // bytes per row block (%128 = 16)
#define FA_KV   (FA_ROW + 32 * FA_RPITCH)    // 144896
#define FA_KVSTG 18432                       // 64 x 72 x 2B x (hi+lo)
#define FA_SMEM (FA_KV + 3 * FA_KVSTG)       // 200192

__global__ void __launch_bounds__(256, 1) fattn() {
    extern __shared__ char sm[];
    const int tid = threadIdx.x, wid = tid >> 5, lane = tid & 31;
    const int r8 = lane & 7, sel = lane >> 3;
    const int q = lane & 3, g = lane >> 2;
    const int i0 = blockIdx.x * 32, bh = blockIdx.y;
    const uint32_t sb = smaddr(sm);

    const __nv_bfloat16* gkh = kb_hi + (size_t)(bh << 10) * 64;
    const __nv_bfloat16* gkl = kb_lo + (size_t)(bh << 10) * 64;

    // Q rows + first two K chunks
    tile_async64<72>((__nv_bfloat16*)(sm + FA_QH), qb_hi + ((size_t)(bh << 10) + i0) * 64, 32, 64, tid);
    tile_async64<72>((__nv_bfloat16*)(sm + FA_QL), qb_lo + ((size_t)(bh << 10) + i0) * 64, 32, 64, tid);
    tile_async64<72>((__nv_bfloat16*)(sm + FA_KV), gkh, 64, 64, tid);
    tile_async64<72>((__nv_bfloat16*)(sm + FA_KV) + 64 * 72, gkl, 64, 64, tid);
    CP_COMMIT();
    tile_async64<72>((__nv_bfloat16*)(sm + FA_KV + FA_KVSTG), gkh + 64 * 64, 64, 64, tid);
    tile_async64<72>((__nv_bfloat16*)(sm + FA_KV + FA_KVSTG) + 64 * 72, gkl + 64 * 64, 64, 64, tid);
    CP_COMMIT();

    uint32_t qfH[2][4][4], qfL[2][4][4];
    bool qloaded = false;

    // ---- sim phase: 16 K-chunks of 64 ----
#pragma unroll 1
    for (int ch = 0; ch < 16; ch++) {
        CP_WAIT1();
        __syncthreads();
        if (ch + 2 < 16) {
            char* st = sm + FA_KV + ((ch + 2) % 3) * FA_KVSTG;
            tile_async64<72>((__nv_bfloat16*)st, gkh + (ch + 2) * 64 * 64, 64, 64, tid);
            tile_async64<72>((__nv_bfloat16*)st + 64 * 72, gkl + (ch + 2) * 64 * 64, 64, 64, tid);
        }
        CP_COMMIT();
        if (!qloaded) {
            qloaded = true;
            const uint32_t qb0 = sb + (((sel & 1) * 8 + r8) * 72 + (sel >> 1) * 8) * 2;
#pragma unroll
            for (int mf = 0; mf < 2; mf++)
#pragma unroll
                for (int ks = 0; ks < 4; ks++) {
                    ldsm4(qfH[mf][ks], qb0 + FA_QH + mf * (16 * 144) + ks * 32);
                    ldsm4(qfL[mf][ks], qb0 + FA_QL + mf * (16 * 144) + ks * 32);
                }
        }
        // K fragments: warp wid covers n8 = rows wid*8..+8 of this chunk
        const uint32_t ka = sb + FA_KV + (ch % 3) * FA_KVSTG +
                            ((wid * 8 + r8) * 72 + sel * 8) * 2;
        uint32_t tH0[4], tH1[4], tL0[4], tL1[4];
        ldsm4(tH0, ka);            // ksteps 0,1 (hi)
        ldsm4(tH1, ka + 64);       // ksteps 2,3 (hi)
        ldsm4(tL0, ka + 9216);
        ldsm4(tL1, ka + 9216 + 64);
        uint32_t bH[4][2] = {{tH0[0], tH0[1]}, {tH0[2], tH0[3]},
                             {tH1[0], tH1[1]}, {tH1[2], tH1[3]}};
        uint32_t bL[4][2] = {{tL0[0], tL0[1]}, {tL0[2], tL0[3]},
                             {tL1[0], tL1[1]}, {tL1[2], tL1[3]}};
        float c[2][4] = {};
#pragma unroll
        for (int ks = 0; ks < 4; ks++)
#pragma unroll
            for (int mf = 0; mf < 2; mf++) {
                mma16816(c[mf], qfH[mf][ks], bH[ks]);
                mma16816(c[mf], qfH[mf][ks], bL[ks]);
                mma16816(c[mf], qfL[mf][ks], bH[ks]);
            }
        // scatter scores to row buffer (fp32)
#pragma unroll
        for (int mf = 0; mf < 2; mf++) {
            int col = ch * 64 + wid * 8 + q * 2;
            float* p0 = (float*)(sm + FA_ROW + (mf * 16 + g) * FA_RPITCH) + col;
            *(float2*)p0 = make_float2(c[mf][0], c[mf][1]);
            float* p1 = (float*)(sm + FA_ROW + (mf * 16 + g + 8) * FA_RPITCH) + col;
            *(float2*)p1 = make_float2(c[mf][2], c[mf][3]);
        }
    }
    __syncthreads();

    // ---- prefetch V chunks 0,1 (land during entmax) ----
    const __nv_bfloat16* gvh = vbT_hi + (size_t)bh * 64 * 1024;
    const __nv_bfloat16* gvl = vbT_lo + (size_t)bh * 64 * 1024;
    tile_async64<72>((__nv_bfloat16*)(sm + FA_KV), gvh, 64, 1024, tid);
    tile_async64<72>((__nv_bfloat16*)(sm + FA_KV) + 64 * 72, gvl, 64, 1024, tid);
    CP_COMMIT();
    tile_async64<72>((__nv_bfloat16*)(sm + FA_KV + FA_KVSTG), gvh + 64, 64, 1024, tid);
    tile_async64<72>((__nv_bfloat16*)(sm + FA_KV + FA_KVSTG) + 64 * 72, gvl + 64, 64, 1024, tid);
    CP_COMMIT();

    // ---- entmax phase: warp handles rows wid*4 .. wid*4+3 ----
#pragma unroll 1
    for (int rr = 0; rr < 4; rr++) {
        const int row = wid * 4 + rr;
        float* rp = (float*)(sm + FA_ROW + row * FA_RPITCH);
        float z[32];
        float m = -1e30f;
#pragma unroll
        for (int blk = 0; blk < 8; blk++) {
            float4 v = *(float4*)(rp + blk * 128 + lane * 4);
            z[blk * 4 + 0] = v.x * 0.5f; z[blk * 4 + 1] = v.y * 0.5f;
            z[blk * 4 + 2] = v.z * 0.5f; z[blk * 4 + 3] = v.w * 0.5f;
            m = fmaxf(m, fmaxf(fmaxf(z[blk * 4], z[blk * 4 + 1]),
                               fmaxf(z[blk * 4 + 2], z[blk * 4 + 3])));
        }
        m = warp_max(m);
#pragma unroll
        for (int i = 0; i < 32; i++) z[i] -= m;

        float tau = -1.0f;
#pragma unroll 1
        for (int it = 0; it < 12; it++) {
            float s1 = 0.f, s2 = 0.f;
#pragma unroll
            for (int i = 0; i < 32; i++) {
                float r = z[i] - tau;
                if (r > 0.f) { s1 += r; s2 = fmaf(r, r, s2); }
            }
            s1 = warp_sum(s1);
            s2 = warp_sum(s2);
            tau += (s2 - 1.0f) / fmaxf(2.0f * s1, 1e-20f);
        }
        // write attn (bf16 hi/lo) in place over this row's buffer
        uint32_t* ah = (uint32_t*)(sm + FA_ROW + row * FA_RPITCH);
        uint32_t* al = (uint32_t*)(sm + FA_ROW + row * FA_RPITCH + 2080);
#pragma unroll
        for (int blk = 0; blk < 8; blk++) {
            float a0 = fmaxf(z[blk * 4 + 0] - tau, 0.f), a1 = fmaxf(z[blk * 4 + 1] - tau, 0.f);
            float a2 = fmaxf(z[blk * 4 + 2] - tau, 0.f), a3 = fmaxf(z[blk * 4 + 3] - tau, 0.f);
            a0 *= a0; a1 *= a1; a2 *= a2; a3 *= a3;
            __nv_bfloat16 l0, l1, l2, l3;
            uint32_t h01 = packsplit(a0, a1, l0, l1);
            uint32_t h23 = packsplit(a2, a3, l2, l3);
            *(uint2*)(ah + blk * 64 + lane * 2) = make_uint2(h01, h23);
            *(uint2*)(al + blk * 64 + lane * 2) = make_uint2(pack2(l0, l1), pack2(l2, l3));
        }
    }
    __syncthreads();

    // ---- AV phase: warps 2(m16) x 4(n16); 16 V chunks of 64 ----
    const int wm0 = (wid & 1) * 16, wn0 = (wid >> 1) * 16;
    float c2[2][4] = {};
    const uint32_t aBase = sb + FA_ROW + (wm0 + (sel & 1) * 8 + r8) * FA_RPITCH +
                           ((sel >> 1) * 8) * 2;
    const uint32_t vOff = ((wn0 + (sel >> 1) * 8 + r8) * 72 + (sel & 1) * 8) * 2;
#pragma unroll 1
    for (int ch = 0; ch < 16; ch++) {
        CP_WAIT1();
        __syncthreads();
        if (ch + 2 < 16) {
            char* st = sm + FA_KV + ((ch + 2) % 3) * FA_KVSTG;
            tile_async64<72>((__nv_bfloat16*)st, gvh + (ch + 2) * 64, 64, 1024, tid);
            tile_async64<72>((__nv_bfloat16*)st + 64 * 72, gvl + (ch + 2) * 64, 64, 1024, tid);
        }
        CP_COMMIT();
        const uint32_t va = sb + FA_KV + (ch % 3) * FA_KVSTG + vOff;
#pragma unroll
        for (int ks = 0; ks < 4; ks++) {
            uint32_t aH[4], aL[4], tH[4], tL[4];
            uint32_t ao = aBase + (ch * 64 + ks * 16) * 2;
            ldsm4(aH, ao);
            ldsm4(aL, ao + 2080);
            ldsm4(tH, va + ks * 32);
            ldsm4(tL, va + 9216 + ks * 32);
            uint32_t b0H[2] = {tH[0], tH[1]}, b1H[2] = {tH[2], tH[3]};
            uint32_t b0L[2] = {tL[0], tL[1]}, b1L[2] = {tL[2], tL[3]};
            mma16816(c2[0], aH, b0H);
            mma16816(c2[0], aH, b0L);
            mma16816(c2[0], aL, b0H);
            mma16816(c2[1], aH, b1H);
            mma16816(c2[1], aH, b1L);
            mma16816(c2[1], aL, b1H);
        }
    }
    // epilogue -> ob hi/lo, token-major
    const int b = bh >> 3, h = bh & 7;
#pragma unroll
    for (int nf = 0; nf < 2; nf++) {
        int d = wn0 + nf * 8 + q * 2;
#pragma unroll
        for (int half = 0; half < 2; half++) {
            int i = i0 + wm0 + g + half * 8;
            __nv_bfloat16 l0, l1;
            uint32_t hp = packsplit(c2[nf][half * 2], c2[nf][half * 2 + 1], l0, l1);
            size_t base = ((size_t)b * 1024 + i) * 512 + h * 64 + d;
            *(uint32_t*)(ob_hi + base) = hp;
            *(uint32_t*)(ob_lo + base) = pack2(l0, l1);
        }
    }
}

// ---------------------------------------------------------------------------
// final = o @ w_out  (M=4096, N=512, K=512): tile 128x64
// ---------------------------------------------------------------------------
__global__ void __launch_bounds__(256, 2) out_mma(float* __restrict__ out) {
    extern __shared__ __nv_bfloat16 smp[];
    const int tid = threadIdx.x, wid = tid >> 5, lane = tid & 31;
    const int q = lane & 3, g = lane >> 2;
    const int row0 = blockIdx.y * 128, col0 = blockIdx.x * 64;
    const int wm0 = (wid & 3) * 32, wn0 = (wid >> 2) * 32;

    float c[2][4][4] = {};
    pipe_gemm<16>(c, smp,
                  ob_hi + (size_t)row0 * 512, ob_lo + (size_t)row0 * 512,
                  woutT_hi + (size_t)col0 * 512, woutT_lo + (size_t)col0 * 512,
                  512, tid, wm0, wn0, lane);

#pragma unroll
    for (int mf = 0; mf < 2; mf++)
#pragma unroll
        for (int nf = 0; nf < 4; nf++) {
            int n = col0 + wn0 + nf * 8 + q * 2;
#pragma unroll
            for (int half = 0; half < 2; half++) {
                int m = row0 + wm0 + mf * 16 + g + half * 8;
                *(float2*)(out + (size_t)m * 512 + n) =
                    make_float2(c[mf][nf][half * 2], c[mf][nf][half * 2 + 1]);
            }
        }
}

// ---------------------------------------------------------------------------
// kernel_launch
// ---------------------------------------------------------------------------
extern "C" void kernel_launch(void* const* d_in, const int* in_sizes, int n_in,
                              void* d_out, int out_size) {
    (void)in_sizes; (void)n_in; (void)out_size;
    const float* x     = (const float*)d_in[0];
    const float* w_qkv = (const float*)d_in[1];
    const float* w_out = (const float*)d_in[2];
    float* out = (float*)d_out;

    cudaFuncSetAttribute(qkv_mma, cudaFuncAttributeMaxDynamicSharedMemorySize, PIPE_SMEM);
    cudaFuncSetAttribute(fattn,   cudaFuncAttributeMaxDynamicSharedMemorySize, FA_SMEM);
    cudaFuncSetAttribute(out_mma, cudaFuncAttributeMaxDynamicSharedMemorySize, PIPE_SMEM);

    __nv_bfloat16 *wqh, *wql, *woh, *wol;
    cudaGetSymbolAddress((void**)&wqh, wqkvT_hi);
    cudaGetSymbolAddress((void**)&wql, wqkvT_lo);
    cudaGetSymbolAddress((void**)&woh, woutT_hi);
    cudaGetSymbolAddress((void**)&wol, woutT_lo);

    conv_x<<<2048, 256>>>(x);
    conv_w<<<3072, 256>>>(w_qkv, wqh, wql, 1536);
    conv_w<<<1024, 256>>>(w_out, woh, wol, 512);
    qkv_mma<<<dim3(24, 32), 256, PIPE_SMEM>>>();
    vtrans<<<dim3(32, 2, 32), 256>>>();
    fattn<<<dim3(32, 32), 256, FA_SMEM>>>();
    out_mma<<<dim3(8, 32), 256, PIPE_SMEM>>>(out);
}

// round 14
// speedup vs baseline: 1.0056x; 1.0056x over previous
#include <cuda_runtime.h>
#include <cuda_bf16.h>
#include <cstdint>

#define B_   4
#define N_   1024
#define DIM_ 512
#define H_   8
#define D_   64
#define BH_  32
#define QSCALE_ 0.0625f   // 64^-0.5 * 0.5 (entmax pre-scale folded in)

#define S32  40     // smem row stride (elems) for K-chunk-32 tiles
#define S64  72     // smem row stride (elems) for 64-wide tiles

// ---------------------------------------------------------------------------
// Global scratch
// ---------------------------------------------------------------------------
__device__ __nv_bfloat16 xb_hi[4096 * 512], xb_lo[4096 * 512];
__device__ __nv_bfloat16 wqkvT_hi[1536 * 512], wqkvT_lo[1536 * 512];
__device__ __nv_bfloat16 woutT_hi[512 * 512], woutT_lo[512 * 512];
__device__ __nv_bfloat16 qb_hi[BH_ * N_ * D_], qb_lo[BH_ * N_ * D_];
__device__ __nv_bfloat16 kb_hi[BH_ * N_ * D_], kb_lo[BH_ * N_ * D_];
__device__ __nv_bfloat16 vb_hi[BH_ * N_ * D_], vb_lo[BH_ * N_ * D_];
__device__ __nv_bfloat16 vbT_hi[BH_ * D_ * N_], vbT_lo[BH_ * D_ * N_];
__device__ float g_sim[(size_t)BH_ * N_ * N_];   // holds z = sim/2 (Q pre-scaled)
__device__ __nv_bfloat16 ob_hi[4096 * 512], ob_lo[4096 * 512];

// ---------------------------------------------------------------------------
// Helpers
// ---------------------------------------------------------------------------
__device__ __forceinline__ void f32split(float v, __nv_bfloat16& h, __nv_bfloat16& l) {
    h = __float2bfloat16(v);
    l = __float2bfloat16(v - __bfloat162float(h));
}
__device__ __forceinline__ uint32_t pack2(__nv_bfloat16 a, __nv_bfloat16 b) {
    return (uint32_t)__bfloat16_as_ushort(a) |
           ((uint32_t)__bfloat16_as_ushort(b) << 16);
}
__device__ __forceinline__ uint32_t packsplit(float v0, float v1,
                                              __nv_bfloat16& l0, __nv_bfloat16& l1) {
    __nv_bfloat16 h0, h1;
    f32split(v0, h0, l0); f32split(v1, h1, l1);
    return pack2(h0, h1);
}

__device__ __forceinline__ void mma16816(float* c, const uint32_t* a, const uint32_t* b) {
    asm volatile(
        "mma.sync.aligned.m16n8k16.row.col.f32.bf16.bf16.f32 "
        "{%0,%1,%2,%3}, {%4,%5,%6,%7}, {%8,%9}, {%0,%1,%2,%3};"
        : "+f"(c[0]), "+f"(c[1]), "+f"(c[2]), "+f"(c[3])
        : "r"(a[0]), "r"(a[1]), "r"(a[2]), "r"(a[3]), "r"(b[0]), "r"(b[1]));
}

__device__ __forceinline__ uint32_t smaddr(const void* p) {
    uint32_t a;
    asm("{ .reg .u64 t; cvta.to.shared.u64 t, %1; cvt.u32.u64 %0, t; }"
        : "=r"(a) : "l"(p));
    return a;
}
__device__ __forceinline__ void ldsm4(uint32_t* r, uint32_t a) {
    asm volatile("ldmatrix.sync.aligned.m8n8.x4.shared.b16 {%0,%1,%2,%3}, [%4];"
                 : "=r"(r[0]), "=r"(r[1]), "=r"(r[2]), "=r"(r[3]) : "r"(a));
}

__device__ __forceinline__ void cpa16(__nv_bfloat16* dst, const __nv_bfloat16* src) {
    uint32_t s;
    asm("{ .reg .u64 t; cvta.to.shared.u64 t, %1; cvt.u32.u64 %0, t; }"
        : "=r"(s) : "l"(dst));
    asm volatile("cp.async.cg.shared.global [%0], [%1], 16;" :: "r"(s), "l"(src));
}
#define CP_COMMIT() asm volatile("cp.async.commit_group;" ::: "memory")
#define CP_WAIT0()  asm volatile("cp.async.wait_group 0;" ::: "memory")
#define CP_WAIT1()  asm volatile("cp.async.wait_group 1;" ::: "memory")

template<int S>
__device__ __forceinline__ void tile_async32(__nv_bfloat16* dst, const __nv_bfloat16* g,
                                             int rows, int gstride, int tid) {
    for (int i = tid; i < rows * 4; i += 256) {
        int r = i >> 2, q = i & 3;
        cpa16(dst + r * S + q * 8, g + (size_t)r * gstride + q * 8);
    }
}
template<int S>
__device__ __forceinline__ void tile_async64(__nv_bfloat16* dst, const __nv_bfloat16* g,
                                             int rows, int gstride, int tid) {
    for (int i = tid; i < rows * 8; i += 256) {
        int r = i >> 3, q = i & 7;
        cpa16(dst + r * S + q * 8, g + (size_t)r * gstride + q * 8);
    }
}

__device__ __forceinline__ float warp_max(float v) {
#pragma unroll
    for (int o = 16; o; o >>= 1) v = fmaxf(v, __shfl_xor_sync(0xffffffffu, v, o));
    return v;
}
__device__ __forceinline__ float warp_sum(float v) {
#pragma unroll
    for (int o = 16; o; o >>= 1) v += __shfl_xor_sync(0xffffffffu, v, o);
    return v;
}

// ---------------------------------------------------------------------------
// Conversion prologue
// ---------------------------------------------------------------------------
__global__ void __launch_bounds__(256) conv_x(const float* __restrict__ x) {
    int i = blockIdx.x * 256 + threadIdx.x;
    float4 v = ((const float4*)x)[i];
    __nv_bfloat16 l0, l1, l2, l3;
    uint32_t h01 = packsplit(v.x, v.y, l0, l1);
    uint32_t h23 = packsplit(v.z, v.w, l2, l3);
    *(uint2*)(xb_hi + (size_t)i * 4) = make_uint2(h01, h23);
    *(uint2*)(xb_lo + (size_t)i * 4) = make_uint2(pack2(l0, l1), pack2(l2, l3));
}

__global__ void __launch_bounds__(256) conv_w(const float* __restrict__ w,
                                              __nv_bfloat16* th, __nv_bfloat16* tl,
                                              int cols) {
    int i = blockIdx.x * 256 + threadIdx.x;       // i = n*512 + k
    int n = i >> 9, k = i & 511;
    float v = w[(size_t)k * cols + n];
    __nv_bfloat16 h, l;
    f32split(v, h, l);
    th[i] = h; tl[i] = l;
}

// ---------------------------------------------------------------------------
// 2x4-warp GEMM core for 128x64 tiles (qkv / out): contiguous AH|AL|BH|BL
// ---------------------------------------------------------------------------
template<int S, int KC>
__device__ __forceinline__ void gemm_tile24(float c[2][4][4], const __nv_bfloat16* st,
                                            int wm0, int wn0, int lane) {
    const int r8 = lane & 7, sel = lane >> 3;
    const uint32_t base = smaddr(st);
    const uint32_t TA = 128 * S * 2, TB = 64 * S * 2;
    const uint32_t aOff = ((wm0 + (sel & 1) * 8 + r8) * S + (sel >> 1) * 8) * 2;
    const uint32_t bOff = ((wn0 + (sel >> 1) * 8 + r8) * S + (sel & 1) * 8) * 2;
    const uint32_t aH0 = base + aOff, aL0 = base + TA + aOff;
    const uint32_t bH0 = base + 2 * TA + bOff, bL0 = base + 2 * TA + TB + bOff;
#pragma unroll
    for (int k0 = 0; k0 < KC; k0 += 16) {
        uint32_t aH[2][4], aL[2][4], bH[4][2], bL[4][2];
#pragma unroll
        for (int mf = 0; mf < 2; mf++) {
            ldsm4(aH[mf], aH0 + mf * (16 * S * 2) + k0 * 2);
            ldsm4(aL[mf], aL0 + mf * (16 * S * 2) + k0 * 2);
        }
#pragma unroll
        for (int p = 0; p < 2; p++) {
            uint32_t t[4];
            ldsm4(t, bH0 + p * (16 * S * 2) + k0 * 2);
            bH[2 * p][0] = t[0]; bH[2 * p][1] = t[1];
            bH[2 * p + 1][0] = t[2]; bH[2 * p + 1][1] = t[3];
            ldsm4(t, bL0 + p * (16 * S * 2) + k0 * 2);
            bL[2 * p][0] = t[0]; bL[2 * p][1] = t[1];
            bL[2 * p + 1][0] = t[2]; bL[2 * p + 1][1] = t[3];
        }
#pragma unroll
        for (int mf = 0; mf < 2; mf++)
#pragma unroll
            for (int nf = 0; nf < 4; nf++) {
                mma16816(c[mf][nf], aH[mf], bH[nf]);
                mma16816(c[mf][nf], aH[mf], bL[nf]);
                mma16816(c[mf][nf], aL[mf], bH[nf]);
            }
    }
}

// Variant with separate A / B smem bases (for av_fused)
__device__ __forceinline__ void gemm_ab24(float c[2][4][4], uint32_t aBase, uint32_t bBase,
                                          int wm0, int wn0, int lane) {
    const int r8 = lane & 7, sel = lane >> 3;
    const uint32_t aOff = ((wm0 + (sel & 1) * 8 + r8) * S32 + (sel >> 1) * 8) * 2;
    const uint32_t bOff = ((wn0 + (sel >> 1) * 8 + r8) * S32 + (sel & 1) * 8) * 2;
    const uint32_t aH0 = aBase + aOff, aL0 = aBase + 128 * S32 * 2 + aOff;
    const uint32_t bH0 = bBase + bOff, bL0 = bBase + 64 * S32 * 2 + bOff;
#pragma unroll
    for (int k0 = 0; k0 < 32; k0 += 16) {
        uint32_t aH[2][4], aL[2][4], bH[4][2], bL[4][2];
#pragma unroll
        for (int mf = 0; mf < 2; mf++) {
            ldsm4(aH[mf], aH0 + mf * (16 * S32 * 2) + k0 * 2);
            ldsm4(aL[mf], aL0 + mf * (16 * S32 * 2) + k0 * 2);
        }
#pragma unroll
        for (int p = 0; p < 2; p++) {
            uint32_t t[4];
            ldsm4(t, bH0 + p * (16 * S32 * 2) + k0 * 2);
            bH[2 * p][0] = t[0]; bH[2 * p][1] = t[1];
            bH[2 * p + 1][0] = t[2]; bH[2 * p + 1][1] = t[3];
            ldsm4(t, bL0 + p * (16 * S32 * 2) + k0 * 2);
            bL[2 * p][0] = t[0]; bL[2 * p][1] = t[1];
            bL[2 * p + 1][0] = t[2]; bL[2 * p + 1][1] = t[3];
        }
#pragma unroll
        for (int mf = 0; mf < 2; mf++)
#pragma unroll
            for (int nf = 0; nf < 4; nf++) {
                mma16816(c[mf][nf], aH[mf], bH[nf]);
                mma16816(c[mf][nf], aH[mf], bL[nf]);
                mma16816(c[mf][nf], aL[mf], bH[nf]);
            }
    }
}

#define STG_E ((2 * 128 + 2 * 64) * S32)
#define PIPE_SMEM (3 * STG_E * 2)

__device__ __forceinline__ void pipe_load(__nv_bfloat16* st,
                                          const __nv_bfloat16* aH, const __nv_bfloat16* aL,
                                          const __nv_bfloat16* bH, const __nv_bfloat16* bL,
                                          int astride, int tid) {
    tile_async32<S32>(st, aH, 128, astride, tid);
    tile_async32<S32>(st + 128 * S32, aL, 128, astride, tid);
    tile_async32<S32>(st + 2 * 128 * S32, bH, 64, astride, tid);
    tile_async32<S32>(st + 2 * 128 * S32 + 64 * S32, bL, 64, astride, tid);
}

template<int NC>
__device__ __forceinline__ void pipe_gemm(float c[2][4][4], __nv_bfloat16* smp,
                                          const __nv_bfloat16* gah, const __nv_bfloat16* gal,
                                          const __nv_bfloat16* gbh, const __nv_bfloat16* gbl,
                                          int astride, int tid, int wm0, int wn0, int lane) {
    pipe_load(smp, gah, gal, gbh, gbl, astride, tid);
    CP_COMMIT();
    pipe_load(smp + STG_E, gah + 32, gal + 32, gbh + 32, gbl + 32, astride, tid);
    CP_COMMIT();
#pragma unroll 1
    for (int ch = 0; ch < NC; ch++) {
        CP_WAIT1();
        __syncthreads();
        if (ch + 2 < NC) {
            int nx = (ch + 2) % 3;
            pipe_load(smp + nx * STG_E, gah + (ch + 2) * 32, gal + (ch + 2) * 32,
                      gbh + (ch + 2) * 32, gbl + (ch + 2) * 32, astride, tid);
        }
        CP_COMMIT();
        gemm_tile24<S32, 32>(c, smp + (ch % 3) * STG_E, wm0, wn0, lane);
        __syncthreads();
    }
}

// ---------------------------------------------------------------------------
// qkv = x @ w_qkv  (M=4096, N=1536, K=512): tile 128x64
// ---------------------------------------------------------------------------
__global__ void __launch_bounds__(256, 2) qkv_mma() {
    extern __shared__ __nv_bfloat16 smp[];
    const int tid = threadIdx.x, wid = tid >> 5, lane = tid & 31;
    const int q = lane & 3, g = lane >> 2;
    const int row0 = blockIdx.y * 128, col0 = blockIdx.x * 64;
    const int wm0 = (wid & 3) * 32, wn0 = (wid >> 2) * 32;

    float c[2][4][4] = {};
    pipe_gemm<16>(c, smp,
                  xb_hi + (size_t)row0 * 512, xb_lo + (size_t)row0 * 512,
                  wqkvT_hi + (size_t)col0 * 512, wqkvT_lo + (size_t)col0 * 512,
                  512, tid, wm0, wn0, lane);

    const int part = col0 >> 9;
    const int head = (col0 >> 6) & 7;
    __nv_bfloat16* dh = part == 0 ? qb_hi : part == 1 ? kb_hi : vb_hi;
    __nv_bfloat16* dl = part == 0 ? qb_lo : part == 1 ? kb_lo : vb_lo;
    const float sc = part == 0 ? QSCALE_ : 1.0f;
#pragma unroll
    for (int mf = 0; mf < 2; mf++)
#pragma unroll
        for (int nf = 0; nf < 4; nf++) {
            int d = wn0 + nf * 8 + q * 2;
#pragma unroll
            for (int half = 0; half < 2; half++) {
                int m = row0 + wm0 + mf * 16 + g + half * 8;
                __nv_bfloat16 l0, l1;
                uint32_t hp = packsplit(c[mf][nf][half * 2] * sc,
                                        c[mf][nf][half * 2 + 1] * sc, l0, l1);
                size_t base = ((size_t)((m >> 10) * 8 + head) * 1024 + (m & 1023)) * 64 + d;
                *(uint32_t*)(dh + base) = hp;
                *(uint32_t*)(dl + base) = pack2(l0, l1);
            }
        }
}

// ---------------------------------------------------------------------------
// V transpose: vb [bh][j][d] -> vbT [bh][d][j]
// ---------------------------------------------------------------------------
__global__ void __launch_bounds__(256) vtrans() {
    __shared__ __nv_bfloat16 th[32][33], tl[32][33];
    const int bh = blockIdx.z, j0 = blockIdx.x * 32, d0 = blockIdx.y * 32;
    const int tx = threadIdx.x & 31, ty = threadIdx.x >> 5;
    const size_t src = ((size_t)bh * 1024 + j0) * 64 + d0;
    for (int r = ty; r < 32; r += 8) {
        th[r][tx] = vb_hi[src + (size_t)r * 64 + tx];
        tl[r][tx] = vb_lo[src + (size_t)r * 64 + tx];
    }
    __syncthreads();
    const size_t dst = ((size_t)bh * 64 + d0) * 1024 + j0;
    for (int r = ty; r < 32; r += 8) {
        vbT_hi[dst + (size_t)r * 1024 + tx] = th[tx][r];
        vbT_lo[dst + (size_t)r * 1024 + tx] = tl[tx][r];
    }
}

// ---------------------------------------------------------------------------
// sim = Q @ K^T per bh (fp32 z out).  CTA 128x128, K=64, 2 CTA/SM
// ---------------------------------------------------------------------------
#define SIM_SMEM (4 * 128 * S64 * 2)       // 73728 B

__global__ void __launch_bounds__(256, 2) sim_mma() {
    extern __shared__ __nv_bfloat16 smp[];
    const int tid = threadIdx.x, wid = tid >> 5, lane = tid & 31;
    const int q = lane & 3, g = lane >> 2;
    const int j0 = blockIdx.x * 128, i0 = blockIdx.y * 128, bh = blockIdx.z;
    const int wm0 = (wid >> 2) * 64, wn0 = (wid & 3) * 32;

    tile_async64<S64>(smp + 0 * 128 * S64, qb_hi + ((size_t)(bh << 10) + i0) * 64, 128, 64, tid);
    tile_async64<S64>(smp + 1 * 128 * S64, qb_lo + ((size_t)(bh << 10) + i0) * 64, 128, 64, tid);
    tile_async64<S64>(smp + 2 * 128 * S64, kb_hi + ((size_t)(bh << 10) + j0) * 64, 128, 64, tid);
    tile_async64<S64>(smp + 3 * 128 * S64, kb_lo + ((size_t)(bh << 10) + j0) * 64, 128, 64, tid);
    CP_COMMIT();
    CP_WAIT0();
    __syncthreads();

    // 4x4 core inline (A,B both 128 rows)
    float c[4][4][4] = {};
    {
        const int r8 = lane & 7, sel = lane >> 3;
        const uint32_t base = smaddr(smp);
        const uint32_t TE = 128 * S64 * 2;
        const uint32_t aOff = ((wm0 + (sel & 1) * 8 + r8) * S64 + (sel >> 1) * 8) * 2;
        const uint32_t bOff = ((wn0 + (sel >> 1) * 8 + r8) * S64 + (sel & 1) * 8) * 2;
        const uint32_t aH0 = base + aOff, aL0 = base + TE + aOff;
        const uint32_t bH0 = base + 2 * TE + bOff, bL0 = base + 3 * TE + bOff;
#pragma unroll
        for (int k0 = 0; k0 < 64; k0 += 16) {
            uint32_t aH[4][4], aL[4][4], bH[4][2], bL[4][2];
#pragma unroll
            for (int mf = 0; mf < 4; mf++) {
                ldsm4(aH[mf], aH0 + mf * (16 * S64 * 2) + k0 * 2);
                ldsm4(aL[mf], aL0 + mf * (16 * S64 * 2) + k0 * 2);
            }
#pragma unroll
            for (int p = 0; p < 2; p++) {
                uint32_t t[4];
                ldsm4(t, bH0 + p * (16 * S64 * 2) + k0 * 2);
                bH[2 * p][0] = t[0]; bH[2 * p][1] = t[1];
                bH[2 * p + 1][0] = t[2]; bH[2 * p + 1][1] = t[3];
                ldsm4(t, bL0 + p * (16 * S64 * 2) + k0 * 2);
                bL[2 * p][0] = t[0]; bL[2 * p][1] = t[1];
                bL[2 * p + 1][0] = t[2]; bL[2 * p + 1][1] = t[3];
            }
#pragma unroll
            for (int mf = 0; mf < 4; mf++)
#pragma unroll
                for (int nf = 0; nf < 4; nf++) {
                    mma16816(c[mf][nf], aH[mf], bH[nf]);
                    mma16816(c[mf][nf], aH[mf], bL[nf]);
                    mma16816(c[mf][nf], aL[mf], bH[nf]);
                }
        }
    }
#pragma unroll
    for (int mf = 0; mf < 4; mf++)
#pragma unroll
        for (int nf = 0; nf < 4; nf++) {
            int j = j0 + wn0 + nf * 8 + q * 2;
#pragma unroll
            for (int half = 0; half < 2; half++) {
                int i = i0 + wm0 + mf * 16 + g + half * 8;
                *(float2*)(g_sim + ((size_t)(bh << 10) + i) * 1024 + j) =
                    make_float2(c[mf][nf][half * 2], c[mf][nf][half * 2 + 1]);
            }
        }
}

// ---------------------------------------------------------------------------
// FUSED entmax + AV.  CTA = (bh, 128 rows), grid (8,32) = 256 CTAs, 2 CTA/SM.
// Phase 1: per-row t = m + tau (Newton), rows streamed through registers.
// Phase 2: AV with A built on the fly: a = (z - t)+^2 -> bf16 hi/lo -> smem.
// ---------------------------------------------------------------------------
#define AV2_T    0
#define AV2_A0   512
#define AV2_ABUF (2 * 128 * S32 * 2)              // 20480 B per A buffer
#define AV2_V0   (AV2_A0 + 2 * AV2_ABUF)          // 41472
#define AV2_VSTG (2 * 64 * S32 * 2)               // 10240 B per V stage
#define AV2_SMEM (AV2_V0 + 3 * AV2_VSTG)          // 72192 B

__global__ void __launch_bounds__(256, 2) av_fused() {
    extern __shared__ char sm[];
    const int tid = threadIdx.x, wid = tid >> 5, lane = tid & 31;
    const int q = lane & 3, g = lane >> 2;
    const int i0 = blockIdx.x * 128, bh = blockIdx.y;
    const uint32_t sb = smaddr(sm);
    float* t_s = (float*)(sm + AV2_T);

    const float* gs = g_sim + ((size_t)(bh << 10) + i0) * 1024;

    // ---- Phase 1: tau per row (warp handles 16 rows) ----
#pragma unroll 1
    for (int rr = 0; rr < 16; rr++) {
        const int row = wid * 16 + rr;
        const float* rp = gs + (size_t)row * 1024;
        float z[32];
        float m = -1e30f;
#pragma unroll
        for (int blk = 0; blk < 8; blk++) {
            float4 v = *(const float4*)(rp + blk * 128 + lane * 4);
            z[blk * 4 + 0] = v.x; z[blk * 4 + 1] = v.y;
            z[blk * 4 + 2] = v.z; z[blk * 4 + 3] = v.w;
            m = fmaxf(m, fmaxf(fmaxf(v.x, v.y), fmaxf(v.z, v.w)));
        }
        m = warp_max(m);
#pragma unroll
        for (int i = 0; i < 32; i++) z[i] -= m;

        float tau = -1.0f;
#pragma unroll 1
        for (int it = 0; it < 12; it++) {
            float s1 = 0.f, s2 = 0.f;
#pragma unroll
            for (int i = 0; i < 32; i++) {
                float r = z[i] - tau;
                if (r > 0.f) { s1 += r; s2 = fmaf(r, r, s2); }
            }
            s1 = warp_sum(s1);
            s2 = warp_sum(s2);
            tau += (s2 - 1.0f) / fmaxf(2.0f * s1, 1e-20f);
        }
        if (lane == 0) t_s[row] = m + tau;
    }

    // ---- prefetch V chunks 0,1 (j-chunks of 32) ----
    const __nv_bfloat16* gvh = vbT_hi + (size_t)bh * 64 * 1024;
    const __nv_bfloat16* gvl = vbT_lo + (size_t)bh * 64 * 1024;
#pragma unroll 1
    for (int s = 0; s < 2; s++) {
        __nv_bfloat16* vs = (__nv_bfloat16*)(sm + AV2_V0 + s * AV2_VSTG);
        tile_async32<S32>(vs, gvh + s * 32, 64, 1024, tid);
        tile_async32<S32>(vs + 64 * S32, gvl + s * 32, 64, 1024, tid);
        CP_COMMIT();
    }
    __syncthreads();   // t_s visible to all

    // ---- Phase 2: AV over 32 j-chunks ----
    const int wm0 = (wid & 3) * 32, wn0 = (wid >> 2) * 32;
    const int tr0 = tid >> 3;           // base row for transform (0..31)
    const int tc0 = (tid & 7) * 4;      // col within chunk
    float c[2][4][4] = {};
#pragma unroll 1
    for (int ch = 0; ch < 32; ch++) {
        CP_WAIT1();
        __syncthreads();                 // V(ch) visible; all MMA(ch-1) retired
        if (ch + 2 < 32) {
            __nv_bfloat16* vs = (__nv_bfloat16*)(sm + AV2_V0 + ((ch + 2) % 3) * AV2_VSTG);
            tile_async32<S32>(vs, gvh + (ch + 2) * 32, 64, 1024, tid);
            tile_async32<S32>(vs + 64 * S32, gvl + (ch + 2) * 32, 64, 1024, tid);
        }
        CP_COMMIT();
        // transform A(ch): 128 rows x 32 cols -> bf16 hi/lo smem
        char* ab = sm + AV2_A0 + (ch & 1) * AV2_ABUF;
#pragma unroll
        for (int k = 0; k < 4; k++) {
            int r = tr0 + 32 * k;
            float4 v = *(const float4*)(gs + (size_t)r * 1024 + ch * 32 + tc0);
            float t = t_s[r];
            float a0 = fmaxf(v.x - t, 0.f), a1 = fmaxf(v.y - t, 0.f);
            float a2 = fmaxf(v.z - t, 0.f), a3 = fmaxf(v.w - t, 0.f);
            a0 *= a0; a1 *= a1; a2 *= a2; a3 *= a3;
            __nv_bfloat16 l0, l1, l2, l3;
            uint32_t h01 = packsplit(a0, a1, l0, l1);
            uint32_t h23 = packsplit(a2, a3, l2, l3);
            *(uint2*)(ab + (r * S32 + tc0) * 2) = make_uint2(h01, h23);
            *(uint2*)(ab + 128 * S32 * 2 + (r * S32 + tc0) * 2) =
                make_uint2(pack2(l0, l1), pack2(l2, l3));
        }
        __syncthreads();                 // A(ch) visible
        gemm_ab24(c, sb + AV2_A0 + (ch & 1) * AV2_ABUF,
                  sb + AV2_V0 + (ch % 3) * AV2_VSTG, wm0, wn0, lane);
    }

    // epilogue -> ob hi/lo, token-major
    const int b = bh >> 3, h = bh & 7;
#pragma unroll
    for (int mf = 0; mf < 2; mf++)
#pragma unroll
        for (int nf = 0; nf < 4; nf++) {
            int d = wn0 + nf * 8 + q * 2;
#pragma unroll
            for (int half = 0; half < 2; half++) {
                int i = i0 + wm0 + mf * 16 + g + half * 8;
                __nv_bfloat16 l0, l1;
                uint32_t hp = packsplit(c[mf][nf][half * 2],
                                        c[mf][nf][half * 2 + 1], l0, l1);
                size_t base = ((size_t)b * 1024 + i) * 512 + h * 64 + d;
                *(uint32_t*)(ob_hi + base) = hp;
                *(uint32_t*)(ob_lo + base) = pack2(l0, l1);
            }
        }
}

// ---------------------------------------------------------------------------
// final = o @ w_out  (M=4096, N=512, K=512): tile 128x64
// ---------------------------------------------------------------------------
__global__ void __launch_bounds__(256, 2) out_mma(float* __restrict__ out) {
    extern __shared__ __nv_bfloat16 smp[];
    const int tid = threadIdx.x, wid = tid >> 5, lane = tid & 31;
    const int q = lane & 3, g = lane >> 2;
    const int row0 = blockIdx.y * 128, col0 = blockIdx.x * 64;
    const int wm0 = (wid & 3) * 32, wn0 = (wid >> 2) * 32;

    float c[2][4][4] = {};
    pipe_gemm<16>(c, smp,
                  ob_hi + (size_t)row0 * 512, ob_lo + (size_t)row0 * 512,
                  woutT_hi + (size_t)col0 * 512, woutT_lo + (size_t)col0 * 512,
                  512, tid, wm0, wn0, lane);

#pragma unroll
    for (int mf = 0; mf < 2; mf++)
#pragma unroll
        for (int nf = 0; nf < 4; nf++) {
            int n = col0 + wn0 + nf * 8 + q * 2;
#pragma unroll
            for (int half = 0; half < 2; half++) {
                int m = row0 + wm0 + mf * 16 + g + half * 8;
                *(float2*)(out + (size_t)m * 512 + n) =
                    make_float2(c[mf][nf][half * 2], c[mf][nf][half * 2 + 1]);
            }
        }
}

// ---------------------------------------------------------------------------
// kernel_launch
// ---------------------------------------------------------------------------
extern "C" void kernel_launch(void* const* d_in, const int* in_sizes, int n_in,
                              void* d_out, int out_size) {
    (void)in_sizes; (void)n_in; (void)out_size;
    const float* x     = (const float*)d_in[0];
    const float* w_qkv = (const float*)d_in[1];
    const float* w_out = (const float*)d_in[2];
    float* out = (float*)d_out;

    cudaFuncSetAttribute(qkv_mma,  cudaFuncAttributeMaxDynamicSharedMemorySize, PIPE_SMEM);
    cudaFuncSetAttribute(sim_mma,  cudaFuncAttributeMaxDynamicSharedMemorySize, SIM_SMEM);
    cudaFuncSetAttribute(av_fused, cudaFuncAttributeMaxDynamicSharedMemorySize, AV2_SMEM);
    cudaFuncSetAttribute(out_mma,  cudaFuncAttributeMaxDynamicSharedMemorySize, PIPE_SMEM);

    __nv_bfloat16 *wqh, *wql, *woh, *wol;
    cudaGetSymbolAddress((void**)&wqh, wqkvT_hi);
    cudaGetSymbolAddress((void**)&wql, wqkvT_lo);
    cudaGetSymbolAddress((void**)&woh, woutT_hi);
    cudaGetSymbolAddress((void**)&wol, woutT_lo);

    conv_x<<<2048, 256>>>(x);
    conv_w<<<3072, 256>>>(w_qkv, wqh, wql, 1536);
    conv_w<<<1024, 256>>>(w_out, woh, wol, 512);
    qkv_mma<<<dim3(24, 32), 256, PIPE_SMEM>>>();
    vtrans<<<dim3(32, 2, 32), 256>>>();
    sim_mma<<<dim3(8, 8, 32), 256, SIM_SMEM>>>();
    av_fused<<<dim3(8, 32), 256, AV2_SMEM>>>();
    out_mma<<<dim3(8, 32), 256, PIPE_SMEM>>>(out);
}

// round 15
// speedup vs baseline: 1.2760x; 1.2689x over previous
#include <cuda_runtime.h>
#include <cuda_bf16.h>
#include <cstdint>

#define B_   4
#define N_   1024
#define DIM_ 512
#define H_   8
#define D_   64
#define BH_  32
#define QSCALE_ 0.0625f   // 64^-0.5 * 0.5 (entmax pre-scale folded in)

#define S32  40     // smem row stride (elems) for K-chunk-32 tiles
#define S64  72     // smem row stride (elems) for K=64 tiles

// ---------------------------------------------------------------------------
// Global scratch
// ---------------------------------------------------------------------------
__device__ __nv_bfloat16 xb_hi[4096 * 512], xb_lo[4096 * 512];
__device__ __nv_bfloat16 wqkvT_hi[1536 * 512], wqkvT_lo[1536 * 512];
__device__ __nv_bfloat16 woutT_hi[512 * 512], woutT_lo[512 * 512];
__device__ __nv_bfloat16 qb_hi[BH_ * N_ * D_], qb_lo[BH_ * N_ * D_];
__device__ __nv_bfloat16 kb_hi[BH_ * N_ * D_], kb_lo[BH_ * N_ * D_];
__device__ __nv_bfloat16 vb_hi[BH_ * N_ * D_], vb_lo[BH_ * N_ * D_];
__device__ __nv_bfloat16 vbT_hi[BH_ * D_ * N_], vbT_lo[BH_ * D_ * N_];
__device__ float g_sim[(size_t)BH_ * N_ * N_];   // holds z (Q pre-scaled by 1/16)
__device__ __nv_bfloat16 ab_hi[(size_t)BH_ * N_ * N_], ab_lo[(size_t)BH_ * N_ * N_];
__device__ __nv_bfloat16 ob_hi[4096 * 512], ob_lo[4096 * 512];

// ---------------------------------------------------------------------------
// Helpers
// ---------------------------------------------------------------------------
__device__ __forceinline__ void f32split(float v, __nv_bfloat16& h, __nv_bfloat16& l) {
    h = __float2bfloat16(v);
    l = __float2bfloat16(v - __bfloat162float(h));
}
__device__ __forceinline__ uint32_t pack2(__nv_bfloat16 a, __nv_bfloat16 b) {
    return (uint32_t)__bfloat16_as_ushort(a) |
           ((uint32_t)__bfloat16_as_ushort(b) << 16);
}
__device__ __forceinline__ uint32_t packsplit(float v0, float v1,
                                              __nv_bfloat16& l0, __nv_bfloat16& l1) {
    __nv_bfloat16 h0, h1;
    f32split(v0, h0, l0); f32split(v1, h1, l1);
    return pack2(h0, h1);
}

__device__ __forceinline__ void mma16816(float* c, const uint32_t* a, const uint32_t* b) {
    asm volatile(
        "mma.sync.aligned.m16n8k16.row.col.f32.bf16.bf16.f32 "
        "{%0,%1,%2,%3}, {%4,%5,%6,%7}, {%8,%9}, {%0,%1,%2,%3};"
        : "+f"(c[0]), "+f"(c[1]), "+f"(c[2]), "+f"(c[3])
        : "r"(a[0]), "r"(a[1]), "r"(a[2]), "r"(a[3]), "r"(b[0]), "r"(b[1]));
}

__device__ __forceinline__ uint32_t smaddr(const void* p) {
    uint32_t a;
    asm("{ .reg .u64 t; cvta.to.shared.u64 t, %1; cvt.u32.u64 %0, t; }"
        : "=r"(a) : "l"(p));
    return a;
}
__device__ __forceinline__ void ldsm4(uint32_t* r, uint32_t a) {
    asm volatile("ldmatrix.sync.aligned.m8n8.x4.shared.b16 {%0,%1,%2,%3}, [%4];"
                 : "=r"(r[0]), "=r"(r[1]), "=r"(r[2]), "=r"(r[3]) : "r"(a));
}

__device__ __forceinline__ void cpa16(__nv_bfloat16* dst, const __nv_bfloat16* src) {
    uint32_t s;
    asm("{ .reg .u64 t; cvta.to.shared.u64 t, %1; cvt.u32.u64 %0, t; }"
        : "=r"(s) : "l"(dst));
    asm volatile("cp.async.cg.shared.global [%0], [%1], 16;" :: "r"(s), "l"(src));
}
#define CP_COMMIT() asm volatile("cp.async.commit_group;" ::: "memory")
#define CP_WAIT0()  asm volatile("cp.async.wait_group 0;" ::: "memory")
#define CP_WAIT1()  asm volatile("cp.async.wait_group 1;" ::: "memory")

// async fill of [rows x 32] tile (stride S)
template<int S>
__device__ __forceinline__ void tile_async32(__nv_bfloat16* dst, const __nv_bfloat16* g,
                                             int rows, int gstride, int tid) {
    for (int i = tid; i < rows * 4; i += 256) {
        int r = i >> 2, q = i & 3;
        cpa16(dst + r * S + q * 8, g + (size_t)r * gstride + q * 8);
    }
}
// async fill of [rows x 64] tile (stride S)
template<int S>
__device__ __forceinline__ void tile_async64(__nv_bfloat16* dst, const __nv_bfloat16* g,
                                             int rows, int gstride, int tid) {
    for (int i = tid; i < rows * 8; i += 256) {
        int r = i >> 3, q = i & 7;
        cpa16(dst + r * S + q * 8, g + (size_t)r * gstride + q * 8);
    }
}

// ---------------------------------------------------------------------------
// Warp GEMM cores (ldmatrix-fed). Tile layout: AH[128xS] AL[128xS] BH[64xS] BL[64xS]
// ---------------------------------------------------------------------------
template<int S, int KC>
__device__ __forceinline__ void gemm_tile24(float c[2][4][4], const __nv_bfloat16* st,
                                            int wm0, int wn0, int lane) {
    const int r8 = lane & 7, sel = lane >> 3;
    const uint32_t base = smaddr(st);
    const uint32_t TA = 128 * S * 2, TB = 64 * S * 2;
    const uint32_t aOff = ((wm0 + (sel & 1) * 8 + r8) * S + (sel >> 1) * 8) * 2;
    const uint32_t bOff = ((wn0 + (sel >> 1) * 8 + r8) * S + (sel & 1) * 8) * 2;
    const uint32_t aH0 = base + aOff, aL0 = base + TA + aOff;
    const uint32_t bH0 = base + 2 * TA + bOff, bL0 = base + 2 * TA + TB + bOff;
#pragma unroll
    for (int k0 = 0; k0 < KC; k0 += 16) {
        uint32_t aH[2][4], aL[2][4], bH[4][2], bL[4][2];
#pragma unroll
        for (int mf = 0; mf < 2; mf++) {
            ldsm4(aH[mf], aH0 + mf * (16 * S * 2) + k0 * 2);
            ldsm4(aL[mf], aL0 + mf * (16 * S * 2) + k0 * 2);
        }
#pragma unroll
        for (int p = 0; p < 2; p++) {
            uint32_t t[4];
            ldsm4(t, bH0 + p * (16 * S * 2) + k0 * 2);
            bH[2 * p][0] = t[0]; bH[2 * p][1] = t[1];
            bH[2 * p + 1][0] = t[2]; bH[2 * p + 1][1] = t[3];
            ldsm4(t, bL0 + p * (16 * S * 2) + k0 * 2);
            bL[2 * p][0] = t[0]; bL[2 * p][1] = t[1];
            bL[2 * p + 1][0] = t[2]; bL[2 * p + 1][1] = t[3];
        }
#pragma unroll
        for (int mf = 0; mf < 2; mf++)
#pragma unroll
            for (int nf = 0; nf < 4; nf++) {
                mma16816(c[mf][nf], aH[mf], bH[nf]);
                mma16816(c[mf][nf], aH[mf], bL[nf]);
                mma16816(c[mf][nf], aL[mf], bH[nf]);
            }
    }
}

// 4x4 core for sim (A,B both 128 rows)
template<int S, int KC>
__device__ __forceinline__ void gemm_tile44(float c[4][4][4], const __nv_bfloat16* st,
                                            int wm0, int wn0, int lane) {
    const int r8 = lane & 7, sel = lane >> 3;
    const uint32_t base = smaddr(st);
    const uint32_t TE = 128 * S * 2;
    const uint32_t aOff = ((wm0 + (sel & 1) * 8 + r8) * S + (sel >> 1) * 8) * 2;
    const uint32_t bOff = ((wn0 + (sel >> 1) * 8 + r8) * S + (sel & 1) * 8) * 2;
    const uint32_t aH0 = base + aOff, aL0 = base + TE + aOff;
    const uint32_t bH0 = base + 2 * TE + bOff, bL0 = base + 3 * TE + bOff;
#pragma unroll
    for (int k0 = 0; k0 < KC; k0 += 16) {
        uint32_t aH[4][4], aL[4][4], bH[4][2], bL[4][2];
#pragma unroll
        for (int mf = 0; mf < 4; mf++) {
            ldsm4(aH[mf], aH0 + mf * (16 * S * 2) + k0 * 2);
            ldsm4(aL[mf], aL0 + mf * (16 * S * 2) + k0 * 2);
        }
#pragma unroll
        for (int p = 0; p < 2; p++) {
            uint32_t t[4];
            ldsm4(t, bH0 + p * (16 * S * 2) + k0 * 2);
            bH[2 * p][0] = t[0]; bH[2 * p][1] = t[1];
            bH[2 * p + 1][0] = t[2]; bH[2 * p + 1][1] = t[3];
            ldsm4(t, bL0 + p * (16 * S * 2) + k0 * 2);
            bL[2 * p][0] = t[0]; bL[2 * p][1] = t[1];
            bL[2 * p + 1][0] = t[2]; bL[2 * p + 1][1] = t[3];
        }
#pragma unroll
        for (int mf = 0; mf < 4; mf++)
#pragma unroll
            for (int nf = 0; nf < 4; nf++) {
                mma16816(c[mf][nf], aH[mf], bH[nf]);
                mma16816(c[mf][nf], aH[mf], bL[nf]);
                mma16816(c[mf][nf], aL[mf], bH[nf]);
            }
    }
}

// ---------------------------------------------------------------------------
// Conversion prologue
// ---------------------------------------------------------------------------
__global__ void __launch_bounds__(256) conv_x(const float* __restrict__ x) {
    int i = blockIdx.x * 256 + threadIdx.x;
    float4 v = ((const float4*)x)[i];
    __nv_bfloat16 l0, l1, l2, l3;
    uint32_t h01 = packsplit(v.x, v.y, l0, l1);
    uint32_t h23 = packsplit(v.z, v.w, l2, l3);
    *(uint2*)(xb_hi + (size_t)i * 4) = make_uint2(h01, h23);
    *(uint2*)(xb_lo + (size_t)i * 4) = make_uint2(pack2(l0, l1), pack2(l2, l3));
}

__global__ void __launch_bounds__(256) conv_w(const float* __restrict__ w,
                                              __nv_bfloat16* th, __nv_bfloat16* tl,
                                              int cols) {
    int i = blockIdx.x * 256 + threadIdx.x;       // i = n*512 + k
    int n = i >> 9, k = i & 511;
    float v = w[(size_t)k * cols + n];
    __nv_bfloat16 h, l;
    f32split(v, h, l);
    th[i] = h; tl[i] = l;
}

// ---------------------------------------------------------------------------
// Shared 3-stage pipelined GEMM body: C[128 x 64] tile, K chunks of 32.
// ---------------------------------------------------------------------------
#define STG_E ((2 * 128 + 2 * 64) * S32)    // 15360 elems = 30720 B
#define PIPE_SMEM (3 * STG_E * 2)           // 92160 B

__device__ __forceinline__ void pipe_load(__nv_bfloat16* st,
                                          const __nv_bfloat16* aH, const __nv_bfloat16* aL,
                                          const __nv_bfloat16* bH, const __nv_bfloat16* bL,
                                          int astride, int tid) {
    tile_async32<S32>(st, aH, 128, astride, tid);
    tile_async32<S32>(st + 128 * S32, aL, 128, astride, tid);
    tile_async32<S32>(st + 2 * 128 * S32, bH, 64, astride, tid);
    tile_async32<S32>(st + 2 * 128 * S32 + 64 * S32, bL, 64, astride, tid);
}

template<int NC>
__device__ __forceinline__ void pipe_gemm(float c[2][4][4], __nv_bfloat16* smp,
                                          const __nv_bfloat16* gah, const __nv_bfloat16* gal,
                                          const __nv_bfloat16* gbh, const __nv_bfloat16* gbl,
                                          int astride, int tid, int wm0, int wn0, int lane) {
    pipe_load(smp, gah, gal, gbh, gbl, astride, tid);
    CP_COMMIT();
    pipe_load(smp + STG_E, gah + 32, gal + 32, gbh + 32, gbl + 32, astride, tid);
    CP_COMMIT();
#pragma unroll 1
    for (int ch = 0; ch < NC; ch++) {
        CP_WAIT1();
        __syncthreads();
        if (ch + 2 < NC) {
            int nx = (ch + 2) % 3;
            pipe_load(smp + nx * STG_E, gah + (ch + 2) * 32, gal + (ch + 2) * 32,
                      gbh + (ch + 2) * 32, gbl + (ch + 2) * 32, astride, tid);
        }
        CP_COMMIT();
        gemm_tile24<S32, 32>(c, smp + (ch % 3) * STG_E, wm0, wn0, lane);
    }
}

// ---------------------------------------------------------------------------
// qkv = x @ w_qkv  (M=4096, N=1536, K=512): tile 128x64, grid 768
// ---------------------------------------------------------------------------
__global__ void __launch_bounds__(256, 2) qkv_mma() {
    extern __shared__ __nv_bfloat16 smp[];
    const int tid = threadIdx.x, wid = tid >> 5, lane = tid & 31;
    const int q = lane & 3, g = lane >> 2;
    const int row0 = blockIdx.y * 128, col0 = blockIdx.x * 64;
    const int wm0 = (wid & 3) * 32, wn0 = (wid >> 2) * 32;

    float c[2][4][4] = {};
    pipe_gemm<16>(c, smp,
                  xb_hi + (size_t)row0 * 512, xb_lo + (size_t)row0 * 512,
                  wqkvT_hi + (size_t)col0 * 512, wqkvT_lo + (size_t)col0 * 512,
                  512, tid, wm0, wn0, lane);

    const int part = col0 >> 9;
    const int head = (col0 >> 6) & 7;
    __nv_bfloat16* dh = part == 0 ? qb_hi : part == 1 ? kb_hi : vb_hi;
    __nv_bfloat16* dl = part == 0 ? qb_lo : part == 1 ? kb_lo : vb_lo;
    const float sc = part == 0 ? QSCALE_ : 1.0f;
#pragma unroll
    for (int mf = 0; mf < 2; mf++)
#pragma unroll
        for (int nf = 0; nf < 4; nf++) {
            int d = wn0 + nf * 8 + q * 2;
#pragma unroll
            for (int half = 0; half < 2; half++) {
                int m = row0 + wm0 + mf * 16 + g + half * 8;
                __nv_bfloat16 l0, l1;
                uint32_t hp = packsplit(c[mf][nf][half * 2] * sc,
                                        c[mf][nf][half * 2 + 1] * sc, l0, l1);
                size_t base = ((size_t)((m >> 10) * 8 + head) * 1024 + (m & 1023)) * 64 + d;
                *(uint32_t*)(dh + base) = hp;
                *(uint32_t*)(dl + base) = pack2(l0, l1);
            }
        }
}

// ---------------------------------------------------------------------------
// V transpose
// ---------------------------------------------------------------------------
__global__ void __launch_bounds__(256) vtrans() {
    __shared__ __nv_bfloat16 th[32][33], tl[32][33];
    const int bh = blockIdx.z, j0 = blockIdx.x * 32, d0 = blockIdx.y * 32;
    const int tx = threadIdx.x & 31, ty = threadIdx.x >> 5;
    const size_t src = ((size_t)bh * 1024 + j0) * 64 + d0;
    for (int r = ty; r < 32; r += 8) {
        th[r][tx] = vb_hi[src + (size_t)r * 64 + tx];
        tl[r][tx] = vb_lo[src + (size_t)r * 64 + tx];
    }
    __syncthreads();
    const size_t dst = ((size_t)bh * 64 + d0) * 1024 + j0;
    for (int r = ty; r < 32; r += 8) {
        vbT_hi[dst + (size_t)r * 1024 + tx] = th[tx][r];
        vbT_lo[dst + (size_t)r * 1024 + tx] = tl[tx][r];
    }
}

// ---------------------------------------------------------------------------
// sim = Q @ K^T per bh (z out).  CTA 128x128, K=64 single chunk, 2 CTA/SM
// ---------------------------------------------------------------------------
#define SIM_SMEM (4 * 128 * S64 * 2)       // 73728 B

__global__ void __launch_bounds__(256, 2) sim_mma() {
    extern __shared__ __nv_bfloat16 smp[];
    const int tid = threadIdx.x, wid = tid >> 5, lane = tid & 31;
    const int q = lane & 3, g = lane >> 2;
    const int j0 = blockIdx.x * 128, i0 = blockIdx.y * 128, bh = blockIdx.z;
    const int wm0 = (wid >> 2) * 64, wn0 = (wid & 3) * 32;

    tile_async64<S64>(smp + 0 * 128 * S64, qb_hi + ((size_t)(bh << 10) + i0) * 64, 128, 64, tid);
    tile_async64<S64>(smp + 1 * 128 * S64, qb_lo + ((size_t)(bh << 10) + i0) * 64, 128, 64, tid);
    tile_async64<S64>(smp + 2 * 128 * S64, kb_hi + ((size_t)(bh << 10) + j0) * 64, 128, 64, tid);
    tile_async64<S64>(smp + 3 * 128 * S64, kb_lo + ((size_t)(bh << 10) + j0) * 64, 128, 64, tid);
    CP_COMMIT();
    CP_WAIT0();
    __syncthreads();

    float c[4][4][4] = {};
    gemm_tile44<S64, 64>(c, smp, wm0, wn0, lane);

#pragma unroll
    for (int mf = 0; mf < 4; mf++)
#pragma unroll
        for (int nf = 0; nf < 4; nf++) {
            int j = j0 + wn0 + nf * 8 + q * 2;
#pragma unroll
            for (int half = 0; half < 2; half++) {
                int i = i0 + wm0 + mf * 16 + g + half * 8;
                *(float2*)(g_sim + ((size_t)(bh << 10) + i) * 1024 + j) =
                    make_float2(c[mf][nf][half * 2], c[mf][nf][half * 2 + 1]);
            }
        }
}

// ---------------------------------------------------------------------------
// entmax-1.5: warp per row, 32 elems/thread in regs, Newton (8 iters)
// ---------------------------------------------------------------------------
__device__ __forceinline__ float warp_max(float v) {
#pragma unroll
    for (int o = 16; o; o >>= 1) v = fmaxf(v, __shfl_xor_sync(0xffffffffu, v, o));
    return v;
}
__device__ __forceinline__ float warp_sum(float v) {
#pragma unroll
    for (int o = 16; o; o >>= 1) v += __shfl_xor_sync(0xffffffffu, v, o);
    return v;
}

__global__ void __launch_bounds__(256) entmax_k() {
    const int lane = threadIdx.x & 31, wid = threadIdx.x >> 5;
    const size_t row = (size_t)blockIdx.x * 8 + wid;
    const float* p = g_sim + row * 1024;

    float z[32];
    float m = -1e30f;
#pragma unroll
    for (int j = 0; j < 8; j++) {
        float4 v = ((const float4*)p)[j * 32 + lane];
        z[j * 4 + 0] = v.x; z[j * 4 + 1] = v.y;
        z[j * 4 + 2] = v.z; z[j * 4 + 3] = v.w;
        m = fmaxf(m, fmaxf(fmaxf(v.x, v.y), fmaxf(v.z, v.w)));
    }
    m = warp_max(m);
#pragma unroll
    for (int i = 0; i < 32; i++) z[i] -= m;

    float tau = -1.0f;
#pragma unroll 1
    for (int it = 0; it < 8; it++) {
        float s1 = 0.f, s2 = 0.f;
#pragma unroll
        for (int i = 0; i < 32; i++) {
            float r = z[i] - tau;
            if (r > 0.f) { s1 += r; s2 = fmaf(r, r, s2); }
        }
        s1 = warp_sum(s1);
        s2 = warp_sum(s2);
        tau += __fdividef(s2 - 1.0f, fmaxf(2.0f * s1, 1e-20f));
    }
#pragma unroll
    for (int j = 0; j < 8; j++) {
        float a0 = fmaxf(z[j * 4 + 0] - tau, 0.f), a1 = fmaxf(z[j * 4 + 1] - tau, 0.f);
        float a2 = fmaxf(z[j * 4 + 2] - tau, 0.f), a3 = fmaxf(z[j * 4 + 3] - tau, 0.f);
        a0 *= a0; a1 *= a1; a2 *= a2; a3 *= a3;
        __nv_bfloat16 l0, l1, l2, l3;
        uint32_t h01 = packsplit(a0, a1, l0, l1);
        uint32_t h23 = packsplit(a2, a3, l2, l3);
        size_t base = row * 1024 + (size_t)(j * 32 + lane) * 4;
        *(uint2*)(ab_hi + base) = make_uint2(h01, h23);
        *(uint2*)(ab_lo + base) = make_uint2(pack2(l0, l1), pack2(l2, l3));
    }
}

// ---------------------------------------------------------------------------
// out = attn @ V per bh.  CTA 128x64, 3-stage pipeline, 32 chunks
// ---------------------------------------------------------------------------
__global__ void __launch_bounds__(256, 2) av_mma() {
    extern __shared__ __nv_bfloat16 smp[];
    const int tid = threadIdx.x, wid = tid >> 5, lane = tid & 31;
    const int q = lane & 3, g = lane >> 2;
    const int i0 = blockIdx.x * 128, bh = blockIdx.y;
    const int wm0 = (wid & 3) * 32, wn0 = (wid >> 2) * 32;

    float c[2][4][4] = {};
    pipe_gemm<32>(c, smp,
                  ab_hi + ((size_t)(bh << 10) + i0) * 1024,
                  ab_lo + ((size_t)(bh << 10) + i0) * 1024,
                  vbT_hi + (size_t)bh * 64 * 1024,
                  vbT_lo + (size_t)bh * 64 * 1024,
                  1024, tid, wm0, wn0, lane);

    const int b = bh >> 3, h = bh & 7;
#pragma unroll
    for (int mf = 0; mf < 2; mf++)
#pragma unroll
        for (int nf = 0; nf < 4; nf++) {
            int d = wn0 + nf * 8 + q * 2;
#pragma unroll
            for (int half = 0; half < 2; half++) {
                int i = i0 + wm0 + mf * 16 + g + half * 8;
                __nv_bfloat16 l0, l1;
                uint32_t hp = packsplit(c[mf][nf][half * 2],
                                        c[mf][nf][half * 2 + 1], l0, l1);
                size_t base = ((size_t)b * 1024 + i) * 512 + h * 64 + d;
                *(uint32_t*)(ob_hi + base) = hp;
                *(uint32_t*)(ob_lo + base) = pack2(l0, l1);
            }
        }
}

// ---------------------------------------------------------------------------
// final = o @ w_out  (M=4096, N=512, K=512): tile 128x64, 3-stage
// ---------------------------------------------------------------------------
__global__ void __launch_bounds__(256, 2) out_mma(float* __restrict__ out) {
    extern __shared__ __nv_bfloat16 smp[];
    const int tid = threadIdx.x, wid = tid >> 5, lane = tid & 31;
    const int q = lane & 3, g = lane >> 2;
    const int row0 = blockIdx.y * 128, col0 = blockIdx.x * 64;
    const int wm0 = (wid & 3) * 32, wn0 = (wid >> 2) * 32;

    float c[2][4][4] = {};
    pipe_gemm<16>(c, smp,
                  ob_hi + (size_t)row0 * 512, ob_lo + (size_t)row0 * 512,
                  woutT_hi + (size_t)col0 * 512, woutT_lo + (size_t)col0 * 512,
                  512, tid, wm0, wn0, lane);

#pragma unroll
    for (int mf = 0; mf < 2; mf++)
#pragma unroll
        for (int nf = 0; nf < 4; nf++) {
            int n = col0 + wn0 + nf * 8 + q * 2;
#pragma unroll
            for (int half = 0; half < 2; half++) {
                int m = row0 + wm0 + mf * 16 + g + half * 8;
                *(float2*)(out + (size_t)m * 512 + n) =
                    make_float2(c[mf][nf][half * 2], c[mf][nf][half * 2 + 1]);
            }
        }
}

// ---------------------------------------------------------------------------
// kernel_launch
// ---------------------------------------------------------------------------
extern "C" void kernel_launch(void* const* d_in, const int* in_sizes, int n_in,
                              void* d_out, int out_size) {
    (void)in_sizes; (void)n_in; (void)out_size;
    const float* x     = (const float*)d_in[0];
    const float* w_qkv = (const float*)d_in[1];
    const float* w_out = (const float*)d_in[2];
    float* out = (float*)d_out;

    cudaFuncSetAttribute(qkv_mma, cudaFuncAttributeMaxDynamicSharedMemorySize, PIPE_SMEM);
    cudaFuncSetAttribute(sim_mma, cudaFuncAttributeMaxDynamicSharedMemorySize, SIM_SMEM);
    cudaFuncSetAttribute(av_mma,  cudaFuncAttributeMaxDynamicSharedMemorySize, PIPE_SMEM);
    cudaFuncSetAttribute(out_mma, cudaFuncAttributeMaxDynamicSharedMemorySize, PIPE_SMEM);

    __nv_bfloat16 *wqh, *wql, *woh, *wol;
    cudaGetSymbolAddress((void**)&wqh, wqkvT_hi);
    cudaGetSymbolAddress((void**)&wql, wqkvT_lo);
    cudaGetSymbolAddress((void**)&woh, woutT_hi);
    cudaGetSymbolAddress((void**)&wol, woutT_lo);

    conv_x<<<2048, 256>>>(x);
    conv_w<<<3072, 256>>>(w_qkv, wqh, wql, 1536);
    conv_w<<<1024, 256>>>(w_out, woh, wol, 512);
    qkv_mma<<<dim3(24, 32), 256, PIPE_SMEM>>>();
    vtrans<<<dim3(32, 2, 32), 256>>>();
    sim_mma<<<dim3(8, 8, 32), 256, SIM_SMEM>>>();
    entmax_k<<<4096, 256>>>();
    av_mma<<<dim3(8, 32), 256, PIPE_SMEM>>>();
    out_mma<<<dim3(8, 32), 256, PIPE_SMEM>>>(out);
}

// round 16
// speedup vs baseline: 1.5925x; 1.2480x over previous
#include <cuda_runtime.h>
#include <cuda_fp16.h>
#include <cstdint>

#define B_   4
#define N_   1024
#define DIM_ 512
#define H_   8
#define D_   64
#define BH_  32
#define QSCALE_ 0.0625f   // 64^-0.5 * 0.5 (entmax pre-scale folded in)

#define S32  40     // smem row stride (elems) for K-chunk-32 tiles
#define S64  72     // smem row stride (elems) for K=64 tiles

// ---------------------------------------------------------------------------
// Global scratch (fp16 split: A-side hi-only, B-side hi+lo)
// ---------------------------------------------------------------------------
__device__ __half xb_hi[4096 * 512];
__device__ __half wqkvT_hi[1536 * 512], wqkvT_lo[1536 * 512];
__device__ __half woutT_hi[512 * 512], woutT_lo[512 * 512];
__device__ __half qb_hi[BH_ * N_ * D_];
__device__ __half kb_hi[BH_ * N_ * D_], kb_lo[BH_ * N_ * D_];
__device__ __half vb_hi[BH_ * N_ * D_], vb_lo[BH_ * N_ * D_];
__device__ __half vbT_hi[BH_ * D_ * N_], vbT_lo[BH_ * D_ * N_];
__device__ float g_sim[(size_t)BH_ * N_ * N_];   // z (Q pre-scaled by 1/16)
__device__ __half ab_hi[(size_t)BH_ * N_ * N_];
__device__ __half ob_hi[4096 * 512];

// ---------------------------------------------------------------------------
// Helpers
// ---------------------------------------------------------------------------
__device__ __forceinline__ void f32split(float v, __half& h, __half& l) {
    h = __float2half_rn(v);
    l = __float2half_rn(v - __half2float(h));
}
__device__ __forceinline__ uint32_t pack2(__half a, __half b) {
    return (uint32_t)__half_as_ushort(a) |
           ((uint32_t)__half_as_ushort(b) << 16);
}
__device__ __forceinline__ uint32_t packhi2(float v0, float v1) {
    return pack2(__float2half_rn(v0), __float2half_rn(v1));
}

__device__ __forceinline__ void mma16816(float* c, const uint32_t* a, const uint32_t* b) {
    asm volatile(
        "mma.sync.aligned.m16n8k16.row.col.f32.f16.f16.f32 "
        "{%0,%1,%2,%3}, {%4,%5,%6,%7}, {%8,%9}, {%0,%1,%2,%3};"
        : "+f"(c[0]), "+f"(c[1]), "+f"(c[2]), "+f"(c[3])
        : "r"(a[0]), "r"(a[1]), "r"(a[2]), "r"(a[3]), "r"(b[0]), "r"(b[1]));
}

__device__ __forceinline__ uint32_t smaddr(const void* p) {
    uint32_t a;
    asm("{ .reg .u64 t; cvta.to.shared.u64 t, %1; cvt.u32.u64 %0, t; }"
        : "=r"(a) : "l"(p));
    return a;
}
__device__ __forceinline__ void ldsm4(uint32_t* r, uint32_t a) {
    asm volatile("ldmatrix.sync.aligned.m8n8.x4.shared.b16 {%0,%1,%2,%3}, [%4];"
                 : "=r"(r[0]), "=r"(r[1]), "=r"(r[2]), "=r"(r[3]) : "r"(a));
}

__device__ __forceinline__ void cpa16(__half* dst, const __half* src) {
    uint32_t s;
    asm("{ .reg .u64 t; cvta.to.shared.u64 t, %1; cvt.u32.u64 %0, t; }"
        : "=r"(s) : "l"(dst));
    asm volatile("cp.async.cg.shared.global [%0], [%1], 16;" :: "r"(s), "l"(src));
}
#define CP_COMMIT() asm volatile("cp.async.commit_group;" ::: "memory")
#define CP_WAIT0()  asm volatile("cp.async.wait_group 0;" ::: "memory")
#define CP_WAIT1()  asm volatile("cp.async.wait_group 1;" ::: "memory")

// async fill of [rows x 32] tile (stride S)
template<int S>
__device__ __forceinline__ void tile_async32(__half* dst, const __half* g,
                                             int rows, int gstride, int tid) {
    for (int i = tid; i < rows * 4; i += 256) {
        int r = i >> 2, q = i & 3;
        cpa16(dst + r * S + q * 8, g + (size_t)r * gstride + q * 8);
    }
}
// async fill of [rows x 64] tile (stride S)
template<int S>
__device__ __forceinline__ void tile_async64(__half* dst, const __half* g,
                                             int rows, int gstride, int tid) {
    for (int i = tid; i < rows * 8; i += 256) {
        int r = i >> 3, q = i & 7;
        cpa16(dst + r * S + q * 8, g + (size_t)r * gstride + q * 8);
    }
}

// ---------------------------------------------------------------------------
// Warp GEMM cores (A hi-only; B hi+lo). Layout: A[128xS] BH[64xS] BL[64xS]
// ---------------------------------------------------------------------------
template<int S, int KC>
__device__ __forceinline__ void gemm_tile24(float c[2][4][4], const __half* st,
                                            int wm0, int wn0, int lane) {
    const int r8 = lane & 7, sel = lane >> 3;
    const uint32_t base = smaddr(st);
    const uint32_t TA = 128 * S * 2, TB = 64 * S * 2;
    const uint32_t aOff = ((wm0 + (sel & 1) * 8 + r8) * S + (sel >> 1) * 8) * 2;
    const uint32_t bOff = ((wn0 + (sel >> 1) * 8 + r8) * S + (sel & 1) * 8) * 2;
    const uint32_t a0 = base + aOff;
    const uint32_t bH0 = base + TA + bOff, bL0 = base + TA + TB + bOff;
#pragma unroll
    for (int k0 = 0; k0 < KC; k0 += 16) {
        uint32_t a[2][4], bH[4][2], bL[4][2];
#pragma unroll
        for (int mf = 0; mf < 2; mf++)
            ldsm4(a[mf], a0 + mf * (16 * S * 2) + k0 * 2);
#pragma unroll
        for (int p = 0; p < 2; p++) {
            uint32_t t[4];
            ldsm4(t, bH0 + p * (16 * S * 2) + k0 * 2);
            bH[2 * p][0] = t[0]; bH[2 * p][1] = t[1];
            bH[2 * p + 1][0] = t[2]; bH[2 * p + 1][1] = t[3];
            ldsm4(t, bL0 + p * (16 * S * 2) + k0 * 2);
            bL[2 * p][0] = t[0]; bL[2 * p][1] = t[1];
            bL[2 * p + 1][0] = t[2]; bL[2 * p + 1][1] = t[3];
        }
#pragma unroll
        for (int mf = 0; mf < 2; mf++)
#pragma unroll
            for (int nf = 0; nf < 4; nf++) {
                mma16816(c[mf][nf], a[mf], bH[nf]);
                mma16816(c[mf][nf], a[mf], bL[nf]);
            }
    }
}

// 4x4 core for sim (A 128 rows hi-only; B 128 rows hi+lo)
template<int S, int KC>
__device__ __forceinline__ void gemm_tile44(float c[4][4][4], const __half* st,
                                            int wm0, int wn0, int lane) {
    const int r8 = lane & 7, sel = lane >> 3;
    const uint32_t base = smaddr(st);
    const uint32_t TE = 128 * S * 2;
    const uint32_t aOff = ((wm0 + (sel & 1) * 8 + r8) * S + (sel >> 1) * 8) * 2;
    const uint32_t bOff = ((wn0 + (sel >> 1) * 8 + r8) * S + (sel & 1) * 8) * 2;
    const uint32_t a0 = base + aOff;
    const uint32_t bH0 = base + TE + bOff, bL0 = base + 2 * TE + bOff;
#pragma unroll
    for (int k0 = 0; k0 < KC; k0 += 16) {
        uint32_t a[4][4], bH[4][2], bL[4][2];
#pragma unroll
        for (int mf = 0; mf < 4; mf++)
            ldsm4(a[mf], a0 + mf * (16 * S * 2) + k0 * 2);
#pragma unroll
        for (int p = 0; p < 2; p++) {
            uint32_t t[4];
            ldsm4(t, bH0 + p * (16 * S * 2) + k0 * 2);
            bH[2 * p][0] = t[0]; bH[2 * p][1] = t[1];
            bH[2 * p + 1][0] = t[2]; bH[2 * p + 1][1] = t[3];
            ldsm4(t, bL0 + p * (16 * S * 2) + k0 * 2);
            bL[2 * p][0] = t[0]; bL[2 * p][1] = t[1];
            bL[2 * p + 1][0] = t[2]; bL[2 * p + 1][1] = t[3];
        }
#pragma unroll
        for (int mf = 0; mf < 4; mf++)
#pragma unroll
            for (int nf = 0; nf < 4; nf++) {
                mma16816(c[mf][nf], a[mf], bH[nf]);
                mma16816(c[mf][nf], a[mf], bL[nf]);
            }
    }
}

// ---------------------------------------------------------------------------
// Conversion prologue
// ---------------------------------------------------------------------------
__global__ void __launch_bounds__(256) conv_x(const float* __restrict__ x) {
    int i = blockIdx.x * 256 + threadIdx.x;
    float4 v = ((const float4*)x)[i];
    *(uint2*)(xb_hi + (size_t)i * 4) =
        make_uint2(packhi2(v.x, v.y), packhi2(v.z, v.w));
}

__global__ void __launch_bounds__(256) conv_w(const float* __restrict__ w,
                                              __half* th, __half* tl, int cols) {
    int i = blockIdx.x * 256 + threadIdx.x;       // i = n*512 + k
    int n = i >> 9, k = i & 511;
    float v = w[(size_t)k * cols + n];
    __half h, l;
    f32split(v, h, l);
    th[i] = h; tl[i] = l;
}

// ---------------------------------------------------------------------------
// Shared 3-stage pipelined GEMM body: C[128 x 64] tile, K chunks of 32.
// Stage: A[128xS32] BH[64xS32] BL[64xS32] = 10240 elems
// ---------------------------------------------------------------------------
#define STG_E ((128 + 2 * 64) * S32)        // 10240 elems = 20480 B
#define PIPE_SMEM (3 * STG_E * 2)           // 61440 B

__device__ __forceinline__ void pipe_load(__half* st,
                                          const __half* a,
                                          const __half* bH, const __half* bL,
                                          int astride, int tid) {
    tile_async32<S32>(st, a, 128, astride, tid);
    tile_async32<S32>(st + 128 * S32, bH, 64, astride, tid);
    tile_async32<S32>(st + 128 * S32 + 64 * S32, bL, 64, astride, tid);
}

template<int NC>
__device__ __forceinline__ void pipe_gemm(float c[2][4][4], __half* smp,
                                          const __half* ga,
                                          const __half* gbh, const __half* gbl,
                                          int astride, int tid, int wm0, int wn0, int lane) {
    pipe_load(smp, ga, gbh, gbl, astride, tid);
    CP_COMMIT();
    pipe_load(smp + STG_E, ga + 32, gbh + 32, gbl + 32, astride, tid);
    CP_COMMIT();
#pragma unroll 1
    for (int ch = 0; ch < NC; ch++) {
        CP_WAIT1();
        __syncthreads();
        if (ch + 2 < NC) {
            int nx = (ch + 2) % 3;
            pipe_load(smp + nx * STG_E, ga + (ch + 2) * 32,
                      gbh + (ch + 2) * 32, gbl + (ch + 2) * 32, astride, tid);
        }
        CP_COMMIT();
        gemm_tile24<S32, 32>(c, smp + (ch % 3) * STG_E, wm0, wn0, lane);
    }
}

// ---------------------------------------------------------------------------
// qkv = x @ w_qkv  (M=4096, N=1536, K=512): tile 128x64, grid 768
// ---------------------------------------------------------------------------
__global__ void __launch_bounds__(256, 2) qkv_mma() {
    extern __shared__ __half smp[];
    const int tid = threadIdx.x, wid = tid >> 5, lane = tid & 31;
    const int q = lane & 3, g = lane >> 2;
    const int row0 = blockIdx.y * 128, col0 = blockIdx.x * 64;
    const int wm0 = (wid & 3) * 32, wn0 = (wid >> 2) * 32;

    float c[2][4][4] = {};
    pipe_gemm<16>(c, smp,
                  xb_hi + (size_t)row0 * 512,
                  wqkvT_hi + (size_t)col0 * 512, wqkvT_lo + (size_t)col0 * 512,
                  512, tid, wm0, wn0, lane);

    const int part = col0 >> 9;
    const int head = (col0 >> 6) & 7;
#pragma unroll
    for (int mf = 0; mf < 2; mf++)
#pragma unroll
        for (int nf = 0; nf < 4; nf++) {
            int d = wn0 + nf * 8 + q * 2;
#pragma unroll
            for (int half = 0; half < 2; half++) {
                int m = row0 + wm0 + mf * 16 + g + half * 8;
                float v0 = c[mf][nf][half * 2], v1 = c[mf][nf][half * 2 + 1];
                size_t base = ((size_t)((m >> 10) * 8 + head) * 1024 + (m & 1023)) * 64 + d;
                if (part == 0) {
                    *(uint32_t*)(qb_hi + base) = packhi2(v0 * QSCALE_, v1 * QSCALE_);
                } else {
                    __half h0, h1, l0, l1;
                    f32split(v0, h0, l0); f32split(v1, h1, l1);
                    __half* dh = part == 1 ? kb_hi : vb_hi;
                    __half* dl = part == 1 ? kb_lo : vb_lo;
                    *(uint32_t*)(dh + base) = pack2(h0, h1);
                    *(uint32_t*)(dl + base) = pack2(l0, l1);
                }
            }
        }
}

// ---------------------------------------------------------------------------
// V transpose: vb [bh][j][d] -> vbT [bh][d][j]  (hi + lo)
// ---------------------------------------------------------------------------
__global__ void __launch_bounds__(256) vtrans() {
    __shared__ __half th[32][33], tl[32][33];
    const int bh = blockIdx.z, j0 = blockIdx.x * 32, d0 = blockIdx.y * 32;
    const int tx = threadIdx.x & 31, ty = threadIdx.x >> 5;
    const size_t src = ((size_t)bh * 1024 + j0) * 64 + d0;
    for (int r = ty; r < 32; r += 8) {
        th[r][tx] = vb_hi[src + (size_t)r * 64 + tx];
        tl[r][tx] = vb_lo[src + (size_t)r * 64 + tx];
    }
    __syncthreads();
    const size_t dst = ((size_t)bh * 64 + d0) * 1024 + j0;
    for (int r = ty; r < 32; r += 8) {
        vbT_hi[dst + (size_t)r * 1024 + tx] = th[tx][r];
        vbT_lo[dst + (size_t)r * 1024 + tx] = tl[tx][r];
    }
}

// ---------------------------------------------------------------------------
// sim = Q @ K^T per bh (z out).  CTA 128x128, K=64 single chunk, 2 CTA/SM
// ---------------------------------------------------------------------------
#define SIM_SMEM (3 * 128 * S64 * 2)       // 55296 B

__global__ void __launch_bounds__(256, 2) sim_mma() {
    extern __shared__ __half smp[];
    const int tid = threadIdx.x, wid = tid >> 5, lane = tid & 31;
    const int q = lane & 3, g = lane >> 2;
    const int j0 = blockIdx.x * 128, i0 = blockIdx.y * 128, bh = blockIdx.z;
    const int wm0 = (wid >> 2) * 64, wn0 = (wid & 3) * 32;

    tile_async64<S64>(smp + 0 * 128 * S64, qb_hi + ((size_t)(bh << 10) + i0) * 64, 128, 64, tid);
    tile_async64<S64>(smp + 1 * 128 * S64, kb_hi + ((size_t)(bh << 10) + j0) * 64, 128, 64, tid);
    tile_async64<S64>(smp + 2 * 128 * S64, kb_lo + ((size_t)(bh << 10) + j0) * 64, 128, 64, tid);
    CP_COMMIT();
    CP_WAIT0();
    __syncthreads();

    float c[4][4][4] = {};
    gemm_tile44<S64, 64>(c, smp, wm0, wn0, lane);

#pragma unroll
    for (int mf = 0; mf < 4; mf++)
#pragma unroll
        for (int nf = 0; nf < 4; nf++) {
            int j = j0 + wn0 + nf * 8 + q * 2;
#pragma unroll
            for (int half = 0; half < 2; half++) {
                int i = i0 + wm0 + mf * 16 + g + half * 8;
                *(float2*)(g_sim + ((size_t)(bh << 10) + i) * 1024 + j) =
                    make_float2(c[mf][nf][half * 2], c[mf][nf][half * 2 + 1]);
            }
        }
}

// ---------------------------------------------------------------------------
// entmax-1.5: warp per row, Newton (8 iters), writes attn hi (fp16) only
// ---------------------------------------------------------------------------
__device__ __forceinline__ float warp_max(float v) {
#pragma unroll
    for (int o = 16; o; o >>= 1) v = fmaxf(v, __shfl_xor_sync(0xffffffffu, v, o));
    return v;
}
__device__ __forceinline__ float warp_sum(float v) {
#pragma unroll
    for (int o = 16; o; o >>= 1) v += __shfl_xor_sync(0xffffffffu, v, o);
    return v;
}

__global__ void __launch_bounds__(256) entmax_k() {
    const int lane = threadIdx.x & 31, wid = threadIdx.x >> 5;
    const size_t row = (size_t)blockIdx.x * 8 + wid;
    const float* p = g_sim + row * 1024;

    float z[32];
    float m = -1e30f;
#pragma unroll
    for (int j = 0; j < 8; j++) {
        float4 v = ((const float4*)p)[j * 32 + lane];
        z[j * 4 + 0] = v.x; z[j * 4 + 1] = v.y;
        z[j * 4 + 2] = v.z; z[j * 4 + 3] = v.w;
        m = fmaxf(m, fmaxf(fmaxf(v.x, v.y), fmaxf(v.z, v.w)));
    }
    m = warp_max(m);
#pragma unroll
    for (int i = 0; i < 32; i++) z[i] -= m;

    float tau = -1.0f;
#pragma unroll 1
    for (int it = 0; it < 8; it++) {
        float s1 = 0.f, s2 = 0.f;
#pragma unroll
        for (int i = 0; i < 32; i++) {
            float r = z[i] - tau;
            if (r > 0.f) { s1 += r; s2 = fmaf(r, r, s2); }
        }
        s1 = warp_sum(s1);
        s2 = warp_sum(s2);
        tau += __fdividef(s2 - 1.0f, fmaxf(2.0f * s1, 1e-20f));
    }
#pragma unroll
    for (int j = 0; j < 8; j++) {
        float a0 = fmaxf(z[j * 4 + 0] - tau, 0.f), a1 = fmaxf(z[j * 4 + 1] - tau, 0.f);
        float a2 = fmaxf(z[j * 4 + 2] - tau, 0.f), a3 = fmaxf(z[j * 4 + 3] - tau, 0.f);
        size_t base = row * 1024 + (size_t)(j * 32 + lane) * 4;
        *(uint2*)(ab_hi + base) =
            make_uint2(packhi2(a0 * a0, a1 * a1), packhi2(a2 * a2, a3 * a3));
    }
}

// ---------------------------------------------------------------------------
// out = attn @ V per bh.  CTA 128x64, 3-stage pipeline, 32 chunks
// ---------------------------------------------------------------------------
__global__ void __launch_bounds__(256, 2) av_mma() {
    extern __shared__ __half smp[];
    const int tid = threadIdx.x, wid = tid >> 5, lane = tid & 31;
    const int q = lane & 3, g = lane >> 2;
    const int i0 = blockIdx.x * 128, bh = blockIdx.y;
    const int wm0 = (wid & 3) * 32, wn0 = (wid >> 2) * 32;

    float c[2][4][4] = {};
    pipe_gemm<32>(c, smp,
                  ab_hi + ((size_t)(bh << 10) + i0) * 1024,
                  vbT_hi + (size_t)bh * 64 * 1024,
                  vbT_lo + (size_t)bh * 64 * 1024,
                  1024, tid, wm0, wn0, lane);

    const int b = bh >> 3, h = bh & 7;
#pragma unroll
    for (int mf = 0; mf < 2; mf++)
#pragma unroll
        for (int nf = 0; nf < 4; nf++) {
            int d = wn0 + nf * 8 + q * 2;
#pragma unroll
            for (int half = 0; half < 2; half++) {
                int i = i0 + wm0 + mf * 16 + g + half * 8;
                size_t base = ((size_t)b * 1024 + i) * 512 + h * 64 + d;
                *(uint32_t*)(ob_hi + base) =
                    packhi2(c[mf][nf][half * 2], c[mf][nf][half * 2 + 1]);
            }
        }
}

// ---------------------------------------------------------------------------
// final = o @ w_out  (M=4096, N=512, K=512): tile 128x64, 3-stage
// ---------------------------------------------------------------------------
__global__ void __launch_bounds__(256, 2) out_mma(float* __restrict__ out) {
    extern __shared__ __half smp[];
    const int tid = threadIdx.x, wid = tid >> 5, lane = tid & 31;
    const int q = lane & 3, g = lane >> 2;
    const int row0 = blockIdx.y * 128, col0 = blockIdx.x * 64;
    const int wm0 = (wid & 3) * 32, wn0 = (wid >> 2) * 32;

    float c[2][4][4] = {};
    pipe_gemm<16>(c, smp,
                  ob_hi + (size_t)row0 * 512,
                  woutT_hi + (size_t)col0 * 512, woutT_lo + (size_t)col0 * 512,
                  512, tid, wm0, wn0, lane);

#pragma unroll
    for (int mf = 0; mf < 2; mf++)
#pragma unroll
        for (int nf = 0; nf < 4; nf++) {
            int n = col0 + wn0 + nf * 8 + q * 2;
#pragma unroll
            for (int half = 0; half < 2; half++) {
                int m = row0 + wm0 + mf * 16 + g + half * 8;
                *(float2*)(out + (size_t)m * 512 + n) =
                    make_float2(c[mf][nf][half * 2], c[mf][nf][half * 2 + 1]);
            }
        }
}

// ---------------------------------------------------------------------------
// kernel_launch
// ---------------------------------------------------------------------------
extern "C" void kernel_launch(void* const* d_in, const int* in_sizes, int n_in,
                              void* d_out, int out_size) {
    (void)in_sizes; (void)n_in; (void)out_size;
    const float* x     = (const float*)d_in[0];
    const float* w_qkv = (const float*)d_in[1];
    const float* w_out = (const float*)d_in[2];
    float* out = (float*)d_out;

    cudaFuncSetAttribute(qkv_mma, cudaFuncAttributeMaxDynamicSharedMemorySize, PIPE_SMEM);
    cudaFuncSetAttribute(sim_mma, cudaFuncAttributeMaxDynamicSharedMemorySize, SIM_SMEM);
    cudaFuncSetAttribute(av_mma,  cudaFuncAttributeMaxDynamicSharedMemorySize, PIPE_SMEM);
    cudaFuncSetAttribute(out_mma, cudaFuncAttributeMaxDynamicSharedMemorySize, PIPE_SMEM);

    __half *wqh, *wql, *woh, *wol;
    cudaGetSymbolAddress((void**)&wqh, wqkvT_hi);
    cudaGetSymbolAddress((void**)&wql, wqkvT_lo);
    cudaGetSymbolAddress((void**)&woh, woutT_hi);
    cudaGetSymbolAddress((void**)&wol, woutT_lo);

    conv_x<<<2048, 256>>>(x);
    conv_w<<<3072, 256>>>(w_qkv, wqh, wql, 1536);
    conv_w<<<1024, 256>>>(w_out, woh, wol, 512);
    qkv_mma<<<dim3(24, 32), 256, PIPE_SMEM>>>();
    vtrans<<<dim3(32, 2, 32), 256>>>();
    sim_mma<<<dim3(8, 8, 32), 256, SIM_SMEM>>>();
    entmax_k<<<4096, 256>>>();
    av_mma<<<dim3(8, 32), 256, PIPE_SMEM>>>();
    out_mma<<<dim3(8, 32), 256, PIPE_SMEM>>>(out);
}

// round 17
// speedup vs baseline: 1.6188x; 1.0165x over previous
#include <cuda_runtime.h>
#include <cuda_fp16.h>
#include <cstdint>

#define B_   4
#define N_   1024
#define DIM_ 512
#define H_   8
#define D_   64
#define BH_  32
#define QSCALE_ 0.0625f   // 64^-0.5 * 0.5 (entmax pre-scale folded in)

#define S32  40     // smem row stride (elems) for K-chunk-32 tiles
#define S64  72     // smem row stride (elems) for K-chunk-64 tiles

// ---------------------------------------------------------------------------
// Global scratch (fp16 split: A-side hi-only, B-side hi+lo)
// ---------------------------------------------------------------------------
__device__ __half xb_hi[4096 * 512];
__device__ __half wqkvT_hi[1536 * 512], wqkvT_lo[1536 * 512];
__device__ __half woutT_hi[512 * 512], woutT_lo[512 * 512];
__device__ __half qb_hi[BH_ * N_ * D_];
__device__ __half kb_hi[BH_ * N_ * D_], kb_lo[BH_ * N_ * D_];
__device__ __half vb_hi[BH_ * N_ * D_], vb_lo[BH_ * N_ * D_];
__device__ __half vbT_hi[BH_ * D_ * N_], vbT_lo[BH_ * D_ * N_];
__device__ float g_sim[(size_t)BH_ * N_ * N_];   // z (Q pre-scaled by 1/16)
__device__ __half ab_hi[(size_t)BH_ * N_ * N_];
__device__ __half ob_hi[4096 * 512];

// ---------------------------------------------------------------------------
// Helpers
// ---------------------------------------------------------------------------
__device__ __forceinline__ void f32split(float v, __half& h, __half& l) {
    h = __float2half_rn(v);
    l = __float2half_rn(v - __half2float(h));
}
__device__ __forceinline__ uint32_t pack2(__half a, __half b) {
    return (uint32_t)__half_as_ushort(a) |
           ((uint32_t)__half_as_ushort(b) << 16);
}
__device__ __forceinline__ uint32_t packhi2(float v0, float v1) {
    return pack2(__float2half_rn(v0), __float2half_rn(v1));
}

__device__ __forceinline__ void mma16816(float* c, const uint32_t* a, const uint32_t* b) {
    asm volatile(
        "mma.sync.aligned.m16n8k16.row.col.f32.f16.f16.f32 "
        "{%0,%1,%2,%3}, {%4,%5,%6,%7}, {%8,%9}, {%0,%1,%2,%3};"
        : "+f"(c[0]), "+f"(c[1]), "+f"(c[2]), "+f"(c[3])
        : "r"(a[0]), "r"(a[1]), "r"(a[2]), "r"(a[3]), "r"(b[0]), "r"(b[1]));
}

__device__ __forceinline__ uint32_t smaddr(const void* p) {
    uint32_t a;
    asm("{ .reg .u64 t; cvta.to.shared.u64 t, %1; cvt.u32.u64 %0, t; }"
        : "=r"(a) : "l"(p));
    return a;
}
__device__ __forceinline__ void ldsm4(uint32_t* r, uint32_t a) {
    asm volatile("ldmatrix.sync.aligned.m8n8.x4.shared.b16 {%0,%1,%2,%3}, [%4];"
                 : "=r"(r[0]), "=r"(r[1]), "=r"(r[2]), "=r"(r[3]) : "r"(a));
}

__device__ __forceinline__ void cpa16(__half* dst, const __half* src) {
    uint32_t s;
    asm("{ .reg .u64 t; cvta.to.shared.u64 t, %1; cvt.u32.u64 %0, t; }"
        : "=r"(s) : "l"(dst));
    asm volatile("cp.async.cg.shared.global [%0], [%1], 16;" :: "r"(s), "l"(src));
}
#define CP_COMMIT() asm volatile("cp.async.commit_group;" ::: "memory")
#define CP_WAIT0()  asm volatile("cp.async.wait_group 0;" ::: "memory")
#define CP_WAIT1()  asm volatile("cp.async.wait_group 1;" ::: "memory")

// async fill of [rows x 32] tile (stride S)
template<int S>
__device__ __forceinline__ void tile_async32(__half* dst, const __half* g,
                                             int rows, int gstride, int tid) {
    for (int i = tid; i < rows * 4; i += 256) {
        int r = i >> 2, q = i & 3;
        cpa16(dst + r * S + q * 8, g + (size_t)r * gstride + q * 8);
    }
}
// async fill of [rows x 64] tile (stride S)
template<int S>
__device__ __forceinline__ void tile_async64(__half* dst, const __half* g,
                                             int rows, int gstride, int tid) {
    for (int i = tid; i < rows * 8; i += 256) {
        int r = i >> 3, q = i & 7;
        cpa16(dst + r * S + q * 8, g + (size_t)r * gstride + q * 8);
    }
}

// ---------------------------------------------------------------------------
// 4x4 warp core: A[128xS] hi, BH[128xS], BL[128xS] contiguous
// ---------------------------------------------------------------------------
template<int S, int KC>
__device__ __forceinline__ void gemm_tile44(float c[4][4][4], const __half* st,
                                            int wm0, int wn0, int lane) {
    const int r8 = lane & 7, sel = lane >> 3;
    const uint32_t base = smaddr(st);
    const uint32_t TE = 128 * S * 2;
    const uint32_t aOff = ((wm0 + (sel & 1) * 8 + r8) * S + (sel >> 1) * 8) * 2;
    const uint32_t bOff = ((wn0 + (sel >> 1) * 8 + r8) * S + (sel & 1) * 8) * 2;
    const uint32_t a0 = base + aOff;
    const uint32_t bH0 = base + TE + bOff, bL0 = base + 2 * TE + bOff;
#pragma unroll
    for (int k0 = 0; k0 < KC; k0 += 16) {
        uint32_t a[4][4], bH[4][2], bL[4][2];
#pragma unroll
        for (int mf = 0; mf < 4; mf++)
            ldsm4(a[mf], a0 + mf * (16 * S * 2) + k0 * 2);
#pragma unroll
        for (int p = 0; p < 2; p++) {
            uint32_t t[4];
            ldsm4(t, bH0 + p * (16 * S * 2) + k0 * 2);
            bH[2 * p][0] = t[0]; bH[2 * p][1] = t[1];
            bH[2 * p + 1][0] = t[2]; bH[2 * p + 1][1] = t[3];
            ldsm4(t, bL0 + p * (16 * S * 2) + k0 * 2);
            bL[2 * p][0] = t[0]; bL[2 * p][1] = t[1];
            bL[2 * p + 1][0] = t[2]; bL[2 * p + 1][1] = t[3];
        }
#pragma unroll
        for (int mf = 0; mf < 4; mf++)
#pragma unroll
            for (int nf = 0; nf < 4; nf++) {
                mma16816(c[mf][nf], a[mf], bH[nf]);
                mma16816(c[mf][nf], a[mf], bL[nf]);
            }
    }
}

// 2x4 warp core: A[128xS] hi, BH[64xS], BL[64xS] contiguous
template<int S, int KC>
__device__ __forceinline__ void gemm_tile24(float c[2][4][4], const __half* st,
                                            int wm0, int wn0, int lane) {
    const int r8 = lane & 7, sel = lane >> 3;
    const uint32_t base = smaddr(st);
    const uint32_t TA = 128 * S * 2, TB = 64 * S * 2;
    const uint32_t aOff = ((wm0 + (sel & 1) * 8 + r8) * S + (sel >> 1) * 8) * 2;
    const uint32_t bOff = ((wn0 + (sel >> 1) * 8 + r8) * S + (sel & 1) * 8) * 2;
    const uint32_t a0 = base + aOff;
    const uint32_t bH0 = base + TA + bOff, bL0 = base + TA + TB + bOff;
#pragma unroll
    for (int k0 = 0; k0 < KC; k0 += 16) {
        uint32_t a[2][4], bH[4][2], bL[4][2];
#pragma unroll
        for (int mf = 0; mf < 2; mf++)
            ldsm4(a[mf], a0 + mf * (16 * S * 2) + k0 * 2);
#pragma unroll
        for (int p = 0; p < 2; p++) {
            uint32_t t[4];
            ldsm4(t, bH0 + p * (16 * S * 2) + k0 * 2);
            bH[2 * p][0] = t[0]; bH[2 * p][1] = t[1];
            bH[2 * p + 1][0] = t[2]; bH[2 * p + 1][1] = t[3];
            ldsm4(t, bL0 + p * (16 * S * 2) + k0 * 2);
            bL[2 * p][0] = t[0]; bL[2 * p][1] = t[1];
            bL[2 * p + 1][0] = t[2]; bL[2 * p + 1][1] = t[3];
        }
#pragma unroll
        for (int mf = 0; mf < 2; mf++)
#pragma unroll
            for (int nf = 0; nf < 4; nf++) {
                mma16816(c[mf][nf], a[mf], bH[nf]);
                mma16816(c[mf][nf], a[mf], bL[nf]);
            }
    }
}

// ---------------------------------------------------------------------------
// Conversion prologue
// ---------------------------------------------------------------------------
__global__ void __launch_bounds__(256) conv_x(const float* __restrict__ x) {
    int i = blockIdx.x * 256 + threadIdx.x;
    float4 v = ((const float4*)x)[i];
    *(uint2*)(xb_hi + (size_t)i * 4) =
        make_uint2(packhi2(v.x, v.y), packhi2(v.z, v.w));
}

__global__ void __launch_bounds__(256) conv_w(const float* __restrict__ w,
                                              __half* th, __half* tl, int cols) {
    int i = blockIdx.x * 256 + threadIdx.x;       // i = n*512 + k
    int n = i >> 9, k = i & 511;
    float v = w[(size_t)k * cols + n];
    __half h, l;
    f32split(v, h, l);
    th[i] = h; tl[i] = l;
}

// ---------------------------------------------------------------------------
// qkv = x @ w_qkv  (M=4096, N=1536, K=512): CTA 128x128 (4x4 warps),
// K-chunk 32, 3-stage.  Stage: A[128xS32] BH[128xS32] BL[128xS32]
// ---------------------------------------------------------------------------
#define QSTG_E (3 * 128 * S32)              // 15360 elems = 30720 B
#define QKV_SMEM (3 * QSTG_E * 2)           // 92160 B

__device__ __forceinline__ void qkv_load(__half* st, const __half* a,
                                         const __half* bH, const __half* bL, int tid) {
    tile_async32<S32>(st, a, 128, 512, tid);
    tile_async32<S32>(st + 128 * S32, bH, 128, 512, tid);
    tile_async32<S32>(st + 2 * 128 * S32, bL, 128, 512, tid);
}

__global__ void __launch_bounds__(256, 2) qkv_mma() {
    extern __shared__ __half smp[];
    const int tid = threadIdx.x, wid = tid >> 5, lane = tid & 31;
    const int q = lane & 3, g = lane >> 2;
    const int row0 = blockIdx.y * 128, col0 = blockIdx.x * 128;
    const int wm0 = (wid >> 2) * 64, wn0 = (wid & 3) * 32;

    const __half* ga  = xb_hi + (size_t)row0 * 512;
    const __half* gbh = wqkvT_hi + (size_t)col0 * 512;
    const __half* gbl = wqkvT_lo + (size_t)col0 * 512;

    qkv_load(smp, ga, gbh, gbl, tid);
    CP_COMMIT();
    qkv_load(smp + QSTG_E, ga + 32, gbh + 32, gbl + 32, tid);
    CP_COMMIT();

    float c[4][4][4] = {};
#pragma unroll 1
    for (int ch = 0; ch < 16; ch++) {
        CP_WAIT1();
        __syncthreads();
        if (ch + 2 < 16) {
            int nx = (ch + 2) % 3;
            qkv_load(smp + nx * QSTG_E, ga + (ch + 2) * 32,
                     gbh + (ch + 2) * 32, gbl + (ch + 2) * 32, tid);
        }
        CP_COMMIT();
        gemm_tile44<S32, 32>(c, smp + (ch % 3) * QSTG_E, wm0, wn0, lane);
    }

    const int part = col0 >> 9;
#pragma unroll
    for (int mf = 0; mf < 4; mf++)
#pragma unroll
        for (int nf = 0; nf < 4; nf++) {
            int ncol = col0 + wn0 + nf * 8 + q * 2;
            int head = (ncol >> 6) & 7;
            int d = ncol & 63;
#pragma unroll
            for (int half = 0; half < 2; half++) {
                int m = row0 + wm0 + mf * 16 + g + half * 8;
                float v0 = c[mf][nf][half * 2], v1 = c[mf][nf][half * 2 + 1];
                size_t base = ((size_t)((m >> 10) * 8 + head) * 1024 + (m & 1023)) * 64 + d;
                if (part == 0) {
                    *(uint32_t*)(qb_hi + base) = packhi2(v0 * QSCALE_, v1 * QSCALE_);
                } else {
                    __half h0, h1, l0, l1;
                    f32split(v0, h0, l0); f32split(v1, h1, l1);
                    __half* dh = part == 1 ? kb_hi : vb_hi;
                    __half* dl = part == 1 ? kb_lo : vb_lo;
                    *(uint32_t*)(dh + base) = pack2(h0, h1);
                    *(uint32_t*)(dl + base) = pack2(l0, l1);
                }
            }
        }
}

// ---------------------------------------------------------------------------
// V transpose: vb [bh][j][d] -> vbT [bh][d][j]  (hi + lo)
// ---------------------------------------------------------------------------
__global__ void __launch_bounds__(256) vtrans() {
    __shared__ __half th[32][33], tl[32][33];
    const int bh = blockIdx.z, j0 = blockIdx.x * 32, d0 = blockIdx.y * 32;
    const int tx = threadIdx.x & 31, ty = threadIdx.x >> 5;
    const size_t src = ((size_t)bh * 1024 + j0) * 64 + d0;
    for (int r = ty; r < 32; r += 8) {
        th[r][tx] = vb_hi[src + (size_t)r * 64 + tx];
        tl[r][tx] = vb_lo[src + (size_t)r * 64 + tx];
    }
    __syncthreads();
    const size_t dst = ((size_t)bh * 64 + d0) * 1024 + j0;
    for (int r = ty; r < 32; r += 8) {
        vbT_hi[dst + (size_t)r * 1024 + tx] = th[tx][r];
        vbT_lo[dst + (size_t)r * 1024 + tx] = tl[tx][r];
    }
}

// ---------------------------------------------------------------------------
// sim = Q @ K^T per bh (z out).  CTA 128x128, K=64 single chunk, 2 CTA/SM
// ---------------------------------------------------------------------------
#define SIM_SMEM (3 * 128 * S64 * 2)       // 55296 B

__global__ void __launch_bounds__(256, 2) sim_mma() {
    extern __shared__ __half smp[];
    const int tid = threadIdx.x, wid = tid >> 5, lane = tid & 31;
    const int q = lane & 3, g = lane >> 2;
    const int j0 = blockIdx.x * 128, i0 = blockIdx.y * 128, bh = blockIdx.z;
    const int wm0 = (wid >> 2) * 64, wn0 = (wid & 3) * 32;

    tile_async64<S64>(smp + 0 * 128 * S64, qb_hi + ((size_t)(bh << 10) + i0) * 64, 128, 64, tid);
    tile_async64<S64>(smp + 1 * 128 * S64, kb_hi + ((size_t)(bh << 10) + j0) * 64, 128, 64, tid);
    tile_async64<S64>(smp + 2 * 128 * S64, kb_lo + ((size_t)(bh << 10) + j0) * 64, 128, 64, tid);
    CP_COMMIT();
    CP_WAIT0();
    __syncthreads();

    float c[4][4][4] = {};
    gemm_tile44<S64, 64>(c, smp, wm0, wn0, lane);

#pragma unroll
    for (int mf = 0; mf < 4; mf++)
#pragma unroll
        for (int nf = 0; nf < 4; nf++) {
            int j = j0 + wn0 + nf * 8 + q * 2;
#pragma unroll
            for (int half = 0; half < 2; half++) {
                int i = i0 + wm0 + mf * 16 + g + half * 8;
                *(float2*)(g_sim + ((size_t)(bh << 10) + i) * 1024 + j) =
                    make_float2(c[mf][nf][half * 2], c[mf][nf][half * 2 + 1]);
            }
        }
}

// ---------------------------------------------------------------------------
// entmax-1.5: warp per row, Newton (8 iters), writes attn hi (fp16) only
// ---------------------------------------------------------------------------
__device__ __forceinline__ float warp_max(float v) {
#pragma unroll
    for (int o = 16; o; o >>= 1) v = fmaxf(v, __shfl_xor_sync(0xffffffffu, v, o));
    return v;
}
__device__ __forceinline__ float warp_sum(float v) {
#pragma unroll
    for (int o = 16; o; o >>= 1) v += __shfl_xor_sync(0xffffffffu, v, o);
    return v;
}

__global__ void __launch_bounds__(256) entmax_k() {
    const int lane = threadIdx.x & 31, wid = threadIdx.x >> 5;
    const size_t row = (size_t)blockIdx.x * 8 + wid;
    const float* p = g_sim + row * 1024;

    float z[32];
    float m = -1e30f;
#pragma unroll
    for (int j = 0; j < 8; j++) {
        float4 v = ((const float4*)p)[j * 32 + lane];
        z[j * 4 + 0] = v.x; z[j * 4 + 1] = v.y;
        z[j * 4 + 2] = v.z; z[j * 4 + 3] = v.w;
        m = fmaxf(m, fmaxf(fmaxf(v.x, v.y), fmaxf(v.z, v.w)));
    }
    m = warp_max(m);
#pragma unroll
    for (int i = 0; i < 32; i++) z[i] -= m;

    float tau = -1.0f;
#pragma unroll 1
    for (int it = 0; it < 8; it++) {
        float s1 = 0.f, s2 = 0.f;
#pragma unroll
        for (int i = 0; i < 32; i++) {
            float r = z[i] - tau;
            if (r > 0.f) { s1 += r; s2 = fmaf(r, r, s2); }
        }
        s1 = warp_sum(s1);
        s2 = warp_sum(s2);
        tau += __fdividef(s2 - 1.0f, fmaxf(2.0f * s1, 1e-20f));
    }
#pragma unroll
    for (int j = 0; j < 8; j++) {
        float a0 = fmaxf(z[j * 4 + 0] - tau, 0.f), a1 = fmaxf(z[j * 4 + 1] - tau, 0.f);
        float a2 = fmaxf(z[j * 4 + 2] - tau, 0.f), a3 = fmaxf(z[j * 4 + 3] - tau, 0.f);
        size_t base = row * 1024 + (size_t)(j * 32 + lane) * 4;
        *(uint2*)(ab_hi + base) =
            make_uint2(packhi2(a0 * a0, a1 * a1), packhi2(a2 * a2, a3 * a3));
    }
}

// ---------------------------------------------------------------------------
// Shared 3-stage pipelined GEMM body (2x4 warps), K chunks of 64.
// Stage: A[128xS64] BH[64xS64] BL[64xS64] = 18432 elems
// ---------------------------------------------------------------------------
#define STG64_E ((128 + 2 * 64) * S64)      // 18432 elems = 36864 B
#define PIPE64_SMEM (3 * STG64_E * 2)       // 110592 B

__device__ __forceinline__ void pipe_load64(__half* st, const __half* a,
                                            const __half* bH, const __half* bL,
                                            int astride, int tid) {
    tile_async64<S64>(st, a, 128, astride, tid);
    tile_async64<S64>(st + 128 * S64, bH, 64, astride, tid);
    tile_async64<S64>(st + 128 * S64 + 64 * S64, bL, 64, astride, tid);
}

template<int NC>
__device__ __forceinline__ void pipe_gemm64(float c[2][4][4], __half* smp,
                                            const __half* ga,
                                            const __half* gbh, const __half* gbl,
                                            int astride, int tid, int wm0, int wn0, int lane) {
    pipe_load64(smp, ga, gbh, gbl, astride, tid);
    CP_COMMIT();
    pipe_load64(smp + STG64_E, ga + 64, gbh + 64, gbl + 64, astride, tid);
    CP_COMMIT();
#pragma unroll 1
    for (int ch = 0; ch < NC; ch++) {
        CP_WAIT1();
        __syncthreads();
        if (ch + 2 < NC) {
            int nx = (ch + 2) % 3;
            pipe_load64(smp + nx * STG64_E, ga + (ch + 2) * 64,
                        gbh + (ch + 2) * 64, gbl + (ch + 2) * 64, astride, tid);
        }
        CP_COMMIT();
        gemm_tile24<S64, 64>(c, smp + (ch % 3) * STG64_E, wm0, wn0, lane);
    }
}

// ---------------------------------------------------------------------------
// out = attn @ V per bh.  CTA 128x64, K-chunk 64, 16 chunks
// ---------------------------------------------------------------------------
__global__ void __launch_bounds__(256, 2) av_mma() {
    extern __shared__ __half smp[];
    const int tid = threadIdx.x, wid = tid >> 5, lane = tid & 31;
    const int q = lane & 3, g = lane >> 2;
    const int i0 = blockIdx.x * 128, bh = blockIdx.y;
    const int wm0 = (wid & 3) * 32, wn0 = (wid >> 2) * 32;

    float c[2][4][4] = {};
    pipe_gemm64<16>(c, smp,
                    ab_hi + ((size_t)(bh << 10) + i0) * 1024,
                    vbT_hi + (size_t)bh * 64 * 1024,
                    vbT_lo + (size_t)bh * 64 * 1024,
                    1024, tid, wm0, wn0, lane);

    const int b = bh >> 3, h = bh & 7;
#pragma unroll
    for (int mf = 0; mf < 2; mf++)
#pragma unroll
        for (int nf = 0; nf < 4; nf++) {
            int d = wn0 + nf * 8 + q * 2;
#pragma unroll
            for (int half = 0; half < 2; half++) {
                int i = i0 + wm0 + mf * 16 + g + half * 8;
                size_t base = ((size_t)b * 1024 + i) * 512 + h * 64 + d;
                *(uint32_t*)(ob_hi + base) =
                    packhi2(c[mf][nf][half * 2], c[mf][nf][half * 2 + 1]);
            }
        }
}

// ---------------------------------------------------------------------------
// final = o @ w_out  (M=4096, N=512, K=512): tile 128x64, K-chunk 64, 8 chunks
// ---------------------------------------------------------------------------
__global__ void __launch_bounds__(256, 2) out_mma(float* __restrict__ out) {
    extern __shared__ __half smp[];
    const int tid = threadIdx.x, wid = tid >> 5, lane = tid & 31;
    const int q = lane & 3, g = lane >> 2;
    const int row0 = blockIdx.y * 128, col0 = blockIdx.x * 64;
    const int wm0 = (wid & 3) * 32, wn0 = (wid >> 2) * 32;

    float c[2][4][4] = {};
    pipe_gemm64<8>(c, smp,
                   ob_hi + (size_t)row0 * 512,
                   woutT_hi + (size_t)col0 * 512, woutT_lo + (size_t)col0 * 512,
                   512, tid, wm0, wn0, lane);

#pragma unroll
    for (int mf = 0; mf < 2; mf++)
#pragma unroll
        for (int nf = 0; nf < 4; nf++) {
            int n = col0 + wn0 + nf * 8 + q * 2;
#pragma unroll
            for (int half = 0; half < 2; half++) {
                int m = row0 + wm0 + mf * 16 + g + half * 8;
                *(float2*)(out + (size_t)m * 512 + n) =
                    make_float2(c[mf][nf][half * 2], c[mf][nf][half * 2 + 1]);
            }
        }
}

// ---------------------------------------------------------------------------
// kernel_launch
// ---------------------------------------------------------------------------
extern "C" void kernel_launch(void* const* d_in, const int* in_sizes, int n_in,
                              void* d_out, int out_size) {
    (void)in_sizes; (void)n_in; (void)out_size;
    const float* x     = (const float*)d_in[0];
    const float* w_qkv = (const float*)d_in[1];
    const float* w_out = (const float*)d_in[2];
    float* out = (float*)d_out;

    cudaFuncSetAttribute(qkv_mma, cudaFuncAttributeMaxDynamicSharedMemorySize, QKV_SMEM);
    cudaFuncSetAttribute(sim_mma, cudaFuncAttributeMaxDynamicSharedMemorySize, SIM_SMEM);
    cudaFuncSetAttribute(av_mma,  cudaFuncAttributeMaxDynamicSharedMemorySize, PIPE64_SMEM);
    cudaFuncSetAttribute(out_mma, cudaFuncAttributeMaxDynamicSharedMemorySize, PIPE64_SMEM);

    __half *wqh, *wql, *woh, *wol;
    cudaGetSymbolAddress((void**)&wqh, wqkvT_hi);
    cudaGetSymbolAddress((void**)&wql, wqkvT_lo);
    cudaGetSymbolAddress((void**)&woh, woutT_hi);
    cudaGetSymbolAddress((void**)&wol, woutT_lo);

    conv_x<<<2048, 256>>>(x);
    conv_w<<<3072, 256>>>(w_qkv, wqh, wql, 1536);
    conv_w<<<1024, 256>>>(w_out, woh, wol, 512);
    qkv_mma<<<dim3(12, 32), 256, QKV_SMEM>>>();
    vtrans<<<dim3(32, 2, 32), 256>>>();
    sim_mma<<<dim3(8, 8, 32), 256, SIM_SMEM>>>();
    entmax_k<<<4096, 256>>>();
    av_mma<<<dim3(8, 32), 256, PIPE64_SMEM>>>();
    out_mma<<<dim3(8, 32), 256, PIPE64_SMEM>>>(out);
}